// round 8
// baseline (speedup 1.0000x reference)
#include <cuda_runtime.h>
#include <cuda_fp16.h>
#include <math.h>

#define N_NODES  100000
#define N_EDGES  3200000
#define N_GRAPHS 256
#define CAP      96        // P(in-degree >= 96) ~ e^-41 per node; multiple of 32
#define NPW      16        // nodes per warp in fused gather2 kernel

// -------- scratch (device globals: no allocations allowed) --------
__device__ int    g_deg[N_NODES];                      // out-degree over row (+1 self)
__device__ int    g_cur[N_NODES];                      // CSR fill cursor -> in-degree
__device__ float  g_dis[N_NODES];                      // d_i = rsqrt(deg)
__device__ __align__(16) int g_csr[N_NODES * CAP];     // sources, padded to 32-mult with N_NODES
__device__ __align__(16) __half g_z[(N_NODES + 1) * 32];   // z_i = W1@(d_i*p_i); row N_NODES = 0
__device__ __align__(16) __half g_h1[(N_NODES + 1) * 32];  // h1'_i = d_i*relu(...); row N_NODES = 0
__device__ float  g_pooled[N_GRAPHS * 64];

__device__ __forceinline__ void red_add_s32(int* p, int v) {
    asm volatile("red.global.add.s32 [%0], %1;" :: "l"(p), "r"(v) : "memory");
}

// Padded paired-edge gather: rows pre-padded to multiple of 32 with dummy node.
// Lanes 0-15 take even edges, 16-31 odd; each lane loads one half2 (2 features).
// Fully unrolled 32-edge chunks -> 8 int4 + 16 half2 independent loads in flight.
__device__ __forceinline__ float gather_sum_h2(const int* __restrict__ csr, int padded,
                                               const __half* __restrict__ tbl, int lane) {
    const int grp = lane >> 4;
    const int sub = lane & 15;
    const __half2* t2 = reinterpret_cast<const __half2*>(tbl);
    float ax0 = 0.f, ay0 = 0.f, ax1 = 0.f, ay1 = 0.f;

    for (int p = 0; p < padded; p += 32) {
        const int4* q4 = reinterpret_cast<const int4*>(csr + p);
#pragma unroll
        for (int u = 0; u < 8; u++) {
            int4 q = __ldg(&q4[u]);
            int ra = grp ? q.y : q.x;
            int rb = grp ? q.w : q.z;
            float2 fa = __half22float2(__ldg(&t2[ra * 16 + sub]));
            float2 fb = __half22float2(__ldg(&t2[rb * 16 + sub]));
            ax0 += fa.x; ay0 += fa.y;
            ax1 += fb.x; ay1 += fb.y;
        }
    }
    float ax = ax0 + ax1, ay = ay0 + ay1;
    ax += __shfl_xor_sync(0xffffffff, ax, 16);
    ay += __shfl_xor_sync(0xffffffff, ay, 16);
    float vx = __shfl_sync(0xffffffff, ax, lane >> 1);
    float vy = __shfl_sync(0xffffffff, ay, lane >> 1);
    return (lane & 1) ? vy : vx;
}

// -------- init: deg=1 (self loop), cur=0, pooled=-inf, dummy rows=0 --------
__global__ void k_init() {
    int t = blockIdx.x * blockDim.x + threadIdx.x;
    if (t < N_NODES) { g_deg[t] = 1; g_cur[t] = 0; }
    if (t < N_GRAPHS * 64) reinterpret_cast<int*>(g_pooled)[t] = 0xFF800000;
    if (t < 32) {
        g_z [N_NODES * 32 + t] = __float2half(0.f);
        g_h1[N_NODES * 32 + t] = __float2half(0.f);
    }
}

// -------- build: 4 edges/thread; deg count over row + CSR fill by col --------
__global__ void k_build(const int4* __restrict__ row4, const int4* __restrict__ col4) {
    int t = blockIdx.x * blockDim.x + threadIdx.x;
    if (t >= N_EDGES / 4) return;
    int4 r = row4[t];
    int4 c = col4[t];
    red_add_s32(&g_deg[r.x], 1);
    red_add_s32(&g_deg[r.y], 1);
    red_add_s32(&g_deg[r.z], 1);
    red_add_s32(&g_deg[r.w], 1);
    int l0 = atomicAdd(&g_cur[c.x], 1);
    int l1 = atomicAdd(&g_cur[c.y], 1);
    int l2 = atomicAdd(&g_cur[c.z], 1);
    int l3 = atomicAdd(&g_cur[c.w], 1);
    if (l0 < CAP) g_csr[c.x * CAP + l0] = r.x;
    if (l1 < CAP) g_csr[c.y * CAP + l1] = r.y;
    if (l2 < CAP) g_csr[c.z * CAP + l2] = r.z;
    if (l3 < CAP) g_csr[c.w * CAP + l3] = r.w;
}

// -------- prep: d = rsqrt(deg); z = W1 @ (d*p); pad csr row to 32-mult --------
__global__ void k_prep(const float* __restrict__ pos, const float* __restrict__ W1) {
    int w = (blockIdx.x * blockDim.x + threadIdx.x) >> 5;
    int lane = threadIdx.x & 31;
    if (w >= N_NODES) return;
    float d = rsqrtf((float)g_deg[w]);
    if (lane == 0) g_dis[w] = d;

    // pad [cnt, roundup32(cnt)) with dummy node index
    int cnt = min(g_cur[w], CAP);
    int padded = (cnt + 31) & ~31;
    int j = cnt + lane;
    if (j < padded) g_csr[w * CAP + j] = N_NODES;

    float pj = (lane < 3) ? pos[w * 3 + lane] : 0.f;
    float p0 = __shfl_sync(0xffffffff, pj, 0);
    float p1 = __shfl_sync(0xffffffff, pj, 1);
    float p2 = __shfl_sync(0xffffffff, pj, 2);
    float z = d * (p0 * __ldg(&W1[lane * 3 + 0]) +
                   p1 * __ldg(&W1[lane * 3 + 1]) +
                   p2 * __ldg(&W1[lane * 3 + 2]));
    g_z[w * 32 + lane] = __float2half(z);
}

// -------- layer 1: h1' = d * relu(dc*(sum z_r + z_i) + b1), warp per node --------
__global__ void __launch_bounds__(256, 4) k_gather1(const float* __restrict__ b1) {
    int i = (blockIdx.x * blockDim.x + threadIdx.x) >> 5;
    int lane = threadIdx.x & 31;
    if (i >= N_NODES) return;
    int padded = (min(g_cur[i], CAP) + 31) & ~31;
    float dc = g_dis[i];
    float acc = __half2float(g_z[i * 32 + lane]);           // self loop
    acc += gather_sum_h2(&g_csr[i * CAP], padded, g_z, lane);
    float pre = fmaf(dc, acc, __ldg(&b1[lane]));
    g_h1[i * 32 + lane] = __float2half(dc * fmaxf(pre, 0.f));
}

// -------- layer 2 gather + transform + relu + pooled max, fully fused --------
__global__ void __launch_bounds__(256, 4) k_g2pool(const float* __restrict__ W2,
                                                   const float* __restrict__ b2,
                                                   const int*   __restrict__ batch) {
    __shared__ float2 sW2[32 * 32];     // [k][o] = {W2T[k][o], W2T[k][o+32]}
    int tid = threadIdx.x;
    for (int x = tid; x < 32 * 32; x += 256) {
        int k = x >> 5, o = x & 31;
        sW2[k * 32 + o] = make_float2(W2[o * 32 + k], W2[(o + 32) * 32 + k]);
    }
    __syncthreads();

    int warp = (blockIdx.x * blockDim.x + tid) >> 5;
    int lane = tid & 31;
    int base = warp * NPW;
    if (base >= N_NODES) return;

    float bo0 = __ldg(&b2[lane]);
    float bo1 = __ldg(&b2[lane + 32]);

    int   curg = -1;
    float m0 = 0.f, m1 = 0.f;           // relu >= 0: safe identity

    for (int t = 0; t < NPW; t++) {
        int i = base + t;
        if (i >= N_NODES) break;
        int padded = (min(g_cur[i], CAP) + 31) & ~31;
        float acc = __half2float(g_h1[i * 32 + lane]);      // self loop
        acc += gather_sum_h2(&g_csr[i * CAP], padded, g_h1, lane);
        float agg = g_dis[i] * acc;                         // agg2[lane]

        float acc0 = bo0, acc1 = bo1;
#pragma unroll
        for (int k = 0; k < 32; k++) {
            float a = __shfl_sync(0xffffffff, agg, k);
            float2 w = sW2[k * 32 + lane];
            acc0 = fmaf(a, w.x, acc0);
            acc1 = fmaf(a, w.y, acc1);
        }
        acc0 = fmaxf(acc0, 0.f);
        acc1 = fmaxf(acc1, 0.f);
        int g = batch[i];
        if (g != curg) {
            if (curg >= 0) {
                atomicMax(reinterpret_cast<int*>(&g_pooled[curg * 64 + lane]),
                          __float_as_int(m0));
                atomicMax(reinterpret_cast<int*>(&g_pooled[curg * 64 + lane + 32]),
                          __float_as_int(m1));
            }
            curg = g; m0 = acc0; m1 = acc1;
        } else {
            m0 = fmaxf(m0, acc0);
            m1 = fmaxf(m1, acc1);
        }
    }
    if (curg >= 0) {
        atomicMax(reinterpret_cast<int*>(&g_pooled[curg * 64 + lane]),
                  __float_as_int(m0));
        atomicMax(reinterpret_cast<int*>(&g_pooled[curg * 64 + lane + 32]),
                  __float_as_int(m1));
    }
}

// -------- head: out = pooled @ Wc^T + bc --------
__global__ void k_final(const float* __restrict__ Wc, const float* __restrict__ bc,
                        float* __restrict__ out) {
    int t = blockIdx.x * blockDim.x + threadIdx.x;
    if (t >= N_GRAPHS * 2) return;
    int g = t >> 1;
    int o = t & 1;
    float acc = bc[o];
#pragma unroll
    for (int k = 0; k < 64; k++)
        acc = fmaf(g_pooled[g * 64 + k], Wc[o * 64 + k], acc);
    out[t] = acc;
}

extern "C" void kernel_launch(void* const* d_in, const int* in_sizes, int n_in,
                              void* d_out, int out_size) {
    const float* pos  = (const float*)d_in[0];
    const int*   eidx = (const int*)  d_in[1];
    const int*   bat  = (const int*)  d_in[2];
    const float* W1   = (const float*)d_in[3];
    const float* b1   = (const float*)d_in[4];
    const float* W2   = (const float*)d_in[5];
    const float* b2   = (const float*)d_in[6];
    const float* Wc   = (const float*)d_in[7];
    const float* bc   = (const float*)d_in[8];
    float* out = (float*)d_out;

    const int* row = eidx;             // edge_index[0]
    const int* col = eidx + N_EDGES;   // edge_index[1]

    const int TB = 256;

    k_init <<<(N_NODES + TB - 1) / TB, TB>>>();
    k_build<<<(N_EDGES / 4 + TB - 1) / TB, TB>>>((const int4*)row, (const int4*)col);
    k_prep <<<(N_NODES * 32 + TB - 1) / TB, TB>>>(pos, W1);
    k_gather1<<<(N_NODES * 32 + TB - 1) / TB, TB>>>(b1);
    {
        int warps = (N_NODES + NPW - 1) / NPW;
        int blocks = (warps * 32 + TB - 1) / TB;
        k_g2pool<<<blocks, TB>>>(W2, b2, bat);
    }
    k_final<<<(N_GRAPHS * 2 + TB - 1) / TB, TB>>>(Wc, bc, out);
}

// round 9
// speedup vs baseline: 1.1032x; 1.1032x over previous
#include <cuda_runtime.h>
#include <cuda_fp16.h>
#include <math.h>

#define N_NODES  100000
#define N_EDGES  3200000
#define N_GRAPHS 256
#define CAP      96        // P(in-degree >= 96) ~ e^-41 per node; multiple of 8
#define NPW      16        // nodes per warp in fused gather2 kernel

// -------- scratch (device globals: no allocations allowed) --------
__device__ int    g_deg[N_NODES];                      // out-degree over row (+1 self)
__device__ int    g_cur[N_NODES];                      // CSR fill cursor -> in-degree
__device__ float  g_dis[N_NODES];                      // d_i = rsqrt(deg)
__device__ __align__(16) int g_csr[N_NODES * CAP];     // sources; padded to 8-mult with N_NODES
__device__ __align__(16) float g_ps[N_NODES * 4];      // {d*p0, d*p1, d*p2, d}
__device__ __align__(16) __half g_h1[(N_NODES + 1) * 32];  // h1' = d*relu(...); row N_NODES = 0
__device__ float  g_pooled[N_GRAPHS * 64];

__device__ __forceinline__ void red_add_s32(int* p, int v) {
    asm volatile("red.global.add.s32 [%0], %1;" :: "l"(p), "r"(v) : "memory");
}

// Paired-edge fp16 gather over a CSR row pre-padded to a multiple of 8 with a
// dummy node (all-zero features). Lanes 0-15: even edges, 16-31: odd edges;
// each lane loads one half2 (2 features). fp32 accumulation.
// Returns per-feature sum with lane = feature.
__device__ __forceinline__ float gather_sum_h2(const int* __restrict__ csr, int padded,
                                               const __half* __restrict__ tbl, int lane) {
    const int grp = lane >> 4;
    const int sub = lane & 15;
    const __half2* t2 = reinterpret_cast<const __half2*>(tbl);
    float ax0 = 0.f, ay0 = 0.f, ax1 = 0.f, ay1 = 0.f;

#pragma unroll 2
    for (int p = 0; p < padded; p += 8) {
        int4 q0 = __ldg(reinterpret_cast<const int4*>(csr + p));
        int4 q1 = __ldg(reinterpret_cast<const int4*>(csr + p + 4));
        int ra = grp ? q0.y : q0.x;
        int rb = grp ? q0.w : q0.z;
        int rc = grp ? q1.y : q1.x;
        int rd = grp ? q1.w : q1.z;
        float2 fa = __half22float2(__ldg(&t2[ra * 16 + sub]));
        float2 fb = __half22float2(__ldg(&t2[rb * 16 + sub]));
        float2 fc = __half22float2(__ldg(&t2[rc * 16 + sub]));
        float2 fd = __half22float2(__ldg(&t2[rd * 16 + sub]));
        ax0 += fa.x + fb.x;  ay0 += fa.y + fb.y;
        ax1 += fc.x + fd.x;  ay1 += fc.y + fd.y;
    }
    float ax = ax0 + ax1, ay = ay0 + ay1;
    ax += __shfl_xor_sync(0xffffffff, ax, 16);
    ay += __shfl_xor_sync(0xffffffff, ay, 16);
    float vx = __shfl_sync(0xffffffff, ax, lane >> 1);
    float vy = __shfl_sync(0xffffffff, ay, lane >> 1);
    return (lane & 1) ? vy : vx;
}

// -------- init: deg=1 (self loop), cur=0, pooled=-inf, dummy h1 row=0 --------
__global__ void k_init() {
    int t = blockIdx.x * blockDim.x + threadIdx.x;
    if (t < N_NODES) { g_deg[t] = 1; g_cur[t] = 0; }
    if (t < N_GRAPHS * 64) reinterpret_cast<int*>(g_pooled)[t] = 0xFF800000;
    if (t < 32) g_h1[N_NODES * 32 + t] = __float2half(0.f);
}

// -------- build: 4 edges/thread; deg count over row + CSR fill by col --------
__global__ void k_build(const int4* __restrict__ row4, const int4* __restrict__ col4) {
    int t = blockIdx.x * blockDim.x + threadIdx.x;
    if (t >= N_EDGES / 4) return;
    int4 r = row4[t];
    int4 c = col4[t];
    red_add_s32(&g_deg[r.x], 1);
    red_add_s32(&g_deg[r.y], 1);
    red_add_s32(&g_deg[r.z], 1);
    red_add_s32(&g_deg[r.w], 1);
    int l0 = atomicAdd(&g_cur[c.x], 1);
    int l1 = atomicAdd(&g_cur[c.y], 1);
    int l2 = atomicAdd(&g_cur[c.z], 1);
    int l3 = atomicAdd(&g_cur[c.w], 1);
    if (l0 < CAP) g_csr[c.x * CAP + l0] = r.x;
    if (l1 < CAP) g_csr[c.y * CAP + l1] = r.y;
    if (l2 < CAP) g_csr[c.z * CAP + l2] = r.z;
    if (l3 < CAP) g_csr[c.w * CAP + l3] = r.w;
}

// -------- prep: d = rsqrt(deg); ps = {d*p, d}; pad csr row to 8-mult --------
__global__ void k_prep(const float* __restrict__ pos) {
    int w = (blockIdx.x * blockDim.x + threadIdx.x) >> 5;
    int lane = threadIdx.x & 31;
    if (w >= N_NODES) return;
    float d = rsqrtf((float)g_deg[w]);

    int cnt = min(g_cur[w], CAP);
    int padded = (cnt + 7) & ~7;
    int j = cnt + lane;
    if (lane < 8 && j < padded) g_csr[w * CAP + j] = N_NODES;  // dummy

    if (lane == 0) {
        g_dis[w] = d;
        float p0 = pos[w * 3 + 0], p1 = pos[w * 3 + 1], p2 = pos[w * 3 + 2];
        *reinterpret_cast<float4*>(&g_ps[w * 4]) = make_float4(d * p0, d * p1, d * p2, d);
    }
}

// -------- layer 1: gather 16B ps per edge, shfl-reduce, W1 transform; warp/node --------
__global__ void k_gather1(const float* __restrict__ W1, const float* __restrict__ b1) {
    int i = (blockIdx.x * blockDim.x + threadIdx.x) >> 5;
    int lane = threadIdx.x & 31;
    if (i >= N_NODES) return;
    int cnt = min(g_cur[i], CAP);
    float dc = g_dis[i];

    float a0 = 0.f, a1 = 0.f, a2 = 0.f;
    for (int j = lane; j < cnt; j += 32) {
        int r = __ldg(&g_csr[i * CAP + j]);                  // coalesced across lanes
        float4 ps = *reinterpret_cast<const float4*>(&g_ps[r * 4]);
        a0 += ps.x; a1 += ps.y; a2 += ps.z;
    }
#pragma unroll
    for (int s = 16; s > 0; s >>= 1) {
        a0 += __shfl_xor_sync(0xffffffff, a0, s);
        a1 += __shfl_xor_sync(0xffffffff, a1, s);
        a2 += __shfl_xor_sync(0xffffffff, a2, s);
    }
    // self loop: + d_i * p_i scaled by dc; then overall dc factor
    float4 psc = *reinterpret_cast<const float4*>(&g_ps[i * 4]);
    a0 = dc * (a0 + psc.x);
    a1 = dc * (a1 + psc.y);
    a2 = dc * (a2 + psc.z);

    int o = lane;
    float acc = __ldg(&b1[o]) + a0 * __ldg(&W1[o * 3 + 0])
                              + a1 * __ldg(&W1[o * 3 + 1])
                              + a2 * __ldg(&W1[o * 3 + 2]);
    g_h1[i * 32 + o] = __float2half(dc * fmaxf(acc, 0.f));
}

// -------- layer 2 gather + transform + relu + pooled max, fully fused --------
__global__ void __launch_bounds__(256) k_g2pool(const float* __restrict__ W2,
                                                const float* __restrict__ b2,
                                                const int*   __restrict__ batch) {
    __shared__ float2 sW2[32 * 32];     // [k][o] = {W2T[k][o], W2T[k][o+32]}
    int tid = threadIdx.x;
    for (int x = tid; x < 32 * 32; x += 256) {
        int k = x >> 5, o = x & 31;
        sW2[k * 32 + o] = make_float2(W2[o * 32 + k], W2[(o + 32) * 32 + k]);
    }
    __syncthreads();

    int warp = (blockIdx.x * blockDim.x + tid) >> 5;
    int lane = tid & 31;
    int base = warp * NPW;
    if (base >= N_NODES) return;

    float bo0 = __ldg(&b2[lane]);
    float bo1 = __ldg(&b2[lane + 32]);

    int   curg = -1;
    float m0 = 0.f, m1 = 0.f;           // relu >= 0: safe identity

    for (int t = 0; t < NPW; t++) {
        int i = base + t;
        if (i >= N_NODES) break;
        int padded = (min(g_cur[i], CAP) + 7) & ~7;
        float acc = __half2float(g_h1[i * 32 + lane]);      // self loop
        acc += gather_sum_h2(&g_csr[i * CAP], padded, g_h1, lane);
        float agg = g_dis[i] * acc;                         // agg2[lane]

        float acc0 = bo0, acc1 = bo1;
#pragma unroll
        for (int k = 0; k < 32; k++) {
            float a = __shfl_sync(0xffffffff, agg, k);
            float2 w = sW2[k * 32 + lane];
            acc0 = fmaf(a, w.x, acc0);
            acc1 = fmaf(a, w.y, acc1);
        }
        acc0 = fmaxf(acc0, 0.f);
        acc1 = fmaxf(acc1, 0.f);
        int g = batch[i];
        if (g != curg) {
            if (curg >= 0) {
                atomicMax(reinterpret_cast<int*>(&g_pooled[curg * 64 + lane]),
                          __float_as_int(m0));
                atomicMax(reinterpret_cast<int*>(&g_pooled[curg * 64 + lane + 32]),
                          __float_as_int(m1));
            }
            curg = g; m0 = acc0; m1 = acc1;
        } else {
            m0 = fmaxf(m0, acc0);
            m1 = fmaxf(m1, acc1);
        }
    }
    if (curg >= 0) {
        atomicMax(reinterpret_cast<int*>(&g_pooled[curg * 64 + lane]),
                  __float_as_int(m0));
        atomicMax(reinterpret_cast<int*>(&g_pooled[curg * 64 + lane + 32]),
                  __float_as_int(m1));
    }
}

// -------- head: out = pooled @ Wc^T + bc --------
__global__ void k_final(const float* __restrict__ Wc, const float* __restrict__ bc,
                        float* __restrict__ out) {
    int t = blockIdx.x * blockDim.x + threadIdx.x;
    if (t >= N_GRAPHS * 2) return;
    int g = t >> 1;
    int o = t & 1;
    float acc = bc[o];
#pragma unroll
    for (int k = 0; k < 64; k++)
        acc = fmaf(g_pooled[g * 64 + k], Wc[o * 64 + k], acc);
    out[t] = acc;
}

extern "C" void kernel_launch(void* const* d_in, const int* in_sizes, int n_in,
                              void* d_out, int out_size) {
    const float* pos  = (const float*)d_in[0];
    const int*   eidx = (const int*)  d_in[1];
    const int*   bat  = (const int*)  d_in[2];
    const float* W1   = (const float*)d_in[3];
    const float* b1   = (const float*)d_in[4];
    const float* W2   = (const float*)d_in[5];
    const float* b2   = (const float*)d_in[6];
    const float* Wc   = (const float*)d_in[7];
    const float* bc   = (const float*)d_in[8];
    float* out = (float*)d_out;

    const int* row = eidx;             // edge_index[0]
    const int* col = eidx + N_EDGES;   // edge_index[1]

    const int TB = 256;

    k_init <<<(N_NODES + TB - 1) / TB, TB>>>();
    k_build<<<(N_EDGES / 4 + TB - 1) / TB, TB>>>((const int4*)row, (const int4*)col);
    k_prep <<<(N_NODES * 32 + TB - 1) / TB, TB>>>(pos);
    k_gather1<<<(N_NODES * 32 + TB - 1) / TB, TB>>>(W1, b1);
    {
        int warps = (N_NODES + NPW - 1) / NPW;
        int blocks = (warps * 32 + TB - 1) / TB;
        k_g2pool<<<blocks, TB>>>(W2, b2, bat);
    }
    k_final<<<(N_GRAPHS * 2 + TB - 1) / TB, TB>>>(Wc, bc, out);
}

// round 10
// speedup vs baseline: 1.1423x; 1.0354x over previous
#include <cuda_runtime.h>
#include <cuda_fp16.h>
#include <math.h>

#define N_NODES  100000
#define N_EDGES  3200000
#define N_GRAPHS 256
#define CAP      96        // P(in-degree >= 96) ~ e^-41 per node; multiple of 8
#define NPW      16        // nodes per warp in fused gather2 kernel (even)

// -------- scratch (device globals: no allocations allowed) --------
__device__ int    g_deg[N_NODES];
__device__ int    g_cur[N_NODES];
__device__ float  g_dis[N_NODES];
__device__ __align__(16) int g_csr[N_NODES * CAP];     // sources; padded to 8-mult with N_NODES
__device__ __align__(16) float g_ps[N_NODES * 4];      // {d*p0, d*p1, d*p2, d}
__device__ __align__(16) __half g_h1[(N_NODES + 1) * 32];  // h1' = d*relu(...); row N_NODES = 0
__device__ float  g_pooled[N_GRAPHS * 64];
__device__ int    g_done;                              // last-block counter

__device__ __forceinline__ void red_add_s32(int* p, int v) {
    asm volatile("red.global.add.s32 [%0], %1;" :: "l"(p), "r"(v) : "memory");
}

// Paired-edge fp16 gather over a CSR row pre-padded to a multiple of 8 with a
// dummy node (all-zero features). Lanes 0-15: even edges, 16-31: odd edges;
// each lane loads one half2 (2 features). fp32 accumulation.
__device__ __forceinline__ float gather_sum_h2(const int* __restrict__ csr, int padded,
                                               const __half* __restrict__ tbl, int lane) {
    const int grp = lane >> 4;
    const int sub = lane & 15;
    const __half2* t2 = reinterpret_cast<const __half2*>(tbl);
    float ax0 = 0.f, ay0 = 0.f, ax1 = 0.f, ay1 = 0.f;

#pragma unroll 2
    for (int p = 0; p < padded; p += 8) {
        int4 q0 = __ldg(reinterpret_cast<const int4*>(csr + p));
        int4 q1 = __ldg(reinterpret_cast<const int4*>(csr + p + 4));
        int ra = grp ? q0.y : q0.x;
        int rb = grp ? q0.w : q0.z;
        int rc = grp ? q1.y : q1.x;
        int rd = grp ? q1.w : q1.z;
        float2 fa = __half22float2(__ldg(&t2[ra * 16 + sub]));
        float2 fb = __half22float2(__ldg(&t2[rb * 16 + sub]));
        float2 fc = __half22float2(__ldg(&t2[rc * 16 + sub]));
        float2 fd = __half22float2(__ldg(&t2[rd * 16 + sub]));
        ax0 += fa.x + fb.x;  ay0 += fa.y + fb.y;
        ax1 += fc.x + fd.x;  ay1 += fc.y + fd.y;
    }
    float ax = ax0 + ax1, ay = ay0 + ay1;
    ax += __shfl_xor_sync(0xffffffff, ax, 16);
    ay += __shfl_xor_sync(0xffffffff, ay, 16);
    float vx = __shfl_sync(0xffffffff, ax, lane >> 1);
    float vy = __shfl_sync(0xffffffff, ay, lane >> 1);
    return (lane & 1) ? vy : vx;
}

// -------- init --------
__global__ void k_init() {
    int t = blockIdx.x * blockDim.x + threadIdx.x;
    if (t < N_NODES) { g_deg[t] = 1; g_cur[t] = 0; }
    if (t < N_GRAPHS * 64) reinterpret_cast<int*>(g_pooled)[t] = 0xFF800000;
    if (t < 32) g_h1[N_NODES * 32 + t] = __float2half(0.f);
    if (t == 32) g_done = 0;
}

// -------- build: 4 edges/thread; deg count over row + CSR fill by col --------
__global__ void k_build(const int4* __restrict__ row4, const int4* __restrict__ col4) {
    int t = blockIdx.x * blockDim.x + threadIdx.x;
    if (t >= N_EDGES / 4) return;
    int4 r = row4[t];
    int4 c = col4[t];
    red_add_s32(&g_deg[r.x], 1);
    red_add_s32(&g_deg[r.y], 1);
    red_add_s32(&g_deg[r.z], 1);
    red_add_s32(&g_deg[r.w], 1);
    int l0 = atomicAdd(&g_cur[c.x], 1);
    int l1 = atomicAdd(&g_cur[c.y], 1);
    int l2 = atomicAdd(&g_cur[c.z], 1);
    int l3 = atomicAdd(&g_cur[c.w], 1);
    if (l0 < CAP) g_csr[c.x * CAP + l0] = r.x;
    if (l1 < CAP) g_csr[c.y * CAP + l1] = r.y;
    if (l2 < CAP) g_csr[c.z * CAP + l2] = r.z;
    if (l3 < CAP) g_csr[c.w * CAP + l3] = r.w;
}

// -------- prep: d = rsqrt(deg); ps = {d*p, d}; pad csr row to 8-mult --------
__global__ void k_prep(const float* __restrict__ pos) {
    int w = (blockIdx.x * blockDim.x + threadIdx.x) >> 5;
    int lane = threadIdx.x & 31;
    if (w >= N_NODES) return;
    float d = rsqrtf((float)g_deg[w]);

    int cnt = min(g_cur[w], CAP);
    int padded = (cnt + 7) & ~7;
    int j = cnt + lane;
    if (lane < 8 && j < padded) g_csr[w * CAP + j] = N_NODES;  // dummy

    if (lane == 0) {
        g_dis[w] = d;
        float p0 = pos[w * 3 + 0], p1 = pos[w * 3 + 1], p2 = pos[w * 3 + 2];
        *reinterpret_cast<float4*>(&g_ps[w * 4]) = make_float4(d * p0, d * p1, d * p2, d);
    }
}

// -------- layer 1: gather 16B ps per edge, shfl-reduce, W1 transform; warp/node --------
__global__ void k_gather1(const float* __restrict__ W1, const float* __restrict__ b1) {
    int i = (blockIdx.x * blockDim.x + threadIdx.x) >> 5;
    int lane = threadIdx.x & 31;
    if (i >= N_NODES) return;
    int cnt = min(g_cur[i], CAP);
    float dc = g_dis[i];

    float a0 = 0.f, a1 = 0.f, a2 = 0.f;
    for (int j = lane; j < cnt; j += 32) {
        int r = __ldg(&g_csr[i * CAP + j]);
        float4 ps = *reinterpret_cast<const float4*>(&g_ps[r * 4]);
        a0 += ps.x; a1 += ps.y; a2 += ps.z;
    }
#pragma unroll
    for (int s = 16; s > 0; s >>= 1) {
        a0 += __shfl_xor_sync(0xffffffff, a0, s);
        a1 += __shfl_xor_sync(0xffffffff, a1, s);
        a2 += __shfl_xor_sync(0xffffffff, a2, s);
    }
    float4 psc = *reinterpret_cast<const float4*>(&g_ps[i * 4]);
    a0 = dc * (a0 + psc.x);
    a1 = dc * (a1 + psc.y);
    a2 = dc * (a2 + psc.z);

    int o = lane;
    float acc = __ldg(&b1[o]) + a0 * __ldg(&W1[o * 3 + 0])
                              + a1 * __ldg(&W1[o * 3 + 1])
                              + a2 * __ldg(&W1[o * 3 + 2]);
    g_h1[i * 32 + o] = __float2half(dc * fmaxf(acc, 0.f));
}

#define FLUSH_MAX()                                                                   \
    do { if (curg >= 0) {                                                             \
        atomicMax(reinterpret_cast<int*>(&g_pooled[curg * 64 + lane]),                \
                  __float_as_int(m0));                                                \
        atomicMax(reinterpret_cast<int*>(&g_pooled[curg * 64 + lane + 32]),           \
                  __float_as_int(m1)); } } while (0)

// -------- layer 2 gather + transform + relu + pool + (last block) head --------
__global__ void __launch_bounds__(256) k_g2pool(const float* __restrict__ W2,
                                                const float* __restrict__ b2,
                                                const int*   __restrict__ batch,
                                                const float* __restrict__ Wc,
                                                const float* __restrict__ bc,
                                                float*       __restrict__ out) {
    __shared__ float2 sW2[32 * 32];     // [k][o] = {W2T[k][o], W2T[k][o+32]}
    int tid = threadIdx.x;
    for (int x = tid; x < 32 * 32; x += 256) {
        int k = x >> 5, o = x & 31;
        sW2[k * 32 + o] = make_float2(W2[o * 32 + k], W2[(o + 32) * 32 + k]);
    }
    __syncthreads();

    int warp = (blockIdx.x * blockDim.x + tid) >> 5;
    int lane = tid & 31;
    int base = warp * NPW;

    if (base < N_NODES) {
        float bo0 = __ldg(&b2[lane]);
        float bo1 = __ldg(&b2[lane + 32]);

        int   curg = -1;
        float m0 = 0.f, m1 = 0.f;       // relu >= 0: safe identity

        for (int t = 0; t < NPW; t += 2) {
            int i0 = base + t;
            int i1 = i0 + 1;
            if (i0 >= N_NODES) break;
            bool v1 = (i1 < N_NODES);

            // two independent gathers (loads overlap)
            int pad0 = (min(g_cur[i0], CAP) + 7) & ~7;
            float a = __half2float(g_h1[i0 * 32 + lane]);
            a += gather_sum_h2(&g_csr[i0 * CAP], pad0, g_h1, lane);
            float aggA = g_dis[i0] * a;

            float aggB = 0.f;
            if (v1) {
                int pad1 = (min(g_cur[i1], CAP) + 7) & ~7;
                float b = __half2float(g_h1[i1 * 32 + lane]);
                b += gather_sum_h2(&g_csr[i1 * CAP], pad1, g_h1, lane);
                aggB = g_dis[i1] * b;
            }

            // paired transform: weights LDS amortized across both nodes
            float o00 = bo0, o01 = bo1, o10 = bo0, o11 = bo1;
#pragma unroll
            for (int k = 0; k < 32; k++) {
                float a0 = __shfl_sync(0xffffffff, aggA, k);
                float a1 = __shfl_sync(0xffffffff, aggB, k);
                float2 w = sW2[k * 32 + lane];
                o00 = fmaf(a0, w.x, o00);
                o01 = fmaf(a0, w.y, o01);
                o10 = fmaf(a1, w.x, o10);
                o11 = fmaf(a1, w.y, o11);
            }

            o00 = fmaxf(o00, 0.f); o01 = fmaxf(o01, 0.f);
            int g0 = batch[i0];
            if (g0 != curg) { FLUSH_MAX(); curg = g0; m0 = o00; m1 = o01; }
            else            { m0 = fmaxf(m0, o00); m1 = fmaxf(m1, o01); }

            if (v1) {
                o10 = fmaxf(o10, 0.f); o11 = fmaxf(o11, 0.f);
                int g1 = batch[i1];
                if (g1 != curg) { FLUSH_MAX(); curg = g1; m0 = o10; m1 = o11; }
                else            { m0 = fmaxf(m0, o10); m1 = fmaxf(m1, o11); }
            }
        }
        FLUSH_MAX();
    }

    // ---- last-block head: out = pooled @ Wc^T + bc ----
    __threadfence();
    __shared__ int sLast;
    if (tid == 0) sLast = (atomicAdd(&g_done, 1) == (int)gridDim.x - 1);
    __syncthreads();
    if (sLast) {
        for (int t = tid; t < N_GRAPHS * 2; t += 256) {
            int g = t >> 1;
            int o = t & 1;
            float acc = __ldg(&bc[o]);
#pragma unroll
            for (int k = 0; k < 64; k++)
                acc = fmaf(__ldcg(&g_pooled[g * 64 + k]), __ldg(&Wc[o * 64 + k]), acc);
            out[t] = acc;
        }
    }
}

extern "C" void kernel_launch(void* const* d_in, const int* in_sizes, int n_in,
                              void* d_out, int out_size) {
    const float* pos  = (const float*)d_in[0];
    const int*   eidx = (const int*)  d_in[1];
    const int*   bat  = (const int*)  d_in[2];
    const float* W1   = (const float*)d_in[3];
    const float* b1   = (const float*)d_in[4];
    const float* W2   = (const float*)d_in[5];
    const float* b2   = (const float*)d_in[6];
    const float* Wc   = (const float*)d_in[7];
    const float* bc   = (const float*)d_in[8];
    float* out = (float*)d_out;

    const int* row = eidx;             // edge_index[0]
    const int* col = eidx + N_EDGES;   // edge_index[1]

    const int TB = 256;

    k_init <<<(N_NODES + TB - 1) / TB, TB>>>();
    k_build<<<(N_EDGES / 4 + TB - 1) / TB, TB>>>((const int4*)row, (const int4*)col);
    k_prep <<<(N_NODES * 32 + TB - 1) / TB, TB>>>(pos);
    k_gather1<<<(N_NODES * 32 + TB - 1) / TB, TB>>>(W1, b1);
    {
        int warps = (N_NODES + NPW - 1) / NPW;
        int blocks = (warps * 32 + TB - 1) / TB;
        k_g2pool<<<blocks, TB>>>(W2, b2, bat, Wc, bc, out);
    }
}

// round 11
// speedup vs baseline: 1.2257x; 1.0730x over previous
#include <cuda_runtime.h>
#include <cuda_fp16.h>
#include <math.h>

#define N_NODES  100000
#define N_EDGES  3200000
#define N_GRAPHS 256
#define CAP      96        // P(in-degree >= 96) ~ e^-41 per node; multiple of 8
#define NPW      16        // nodes per warp in gather2
#define NTILE    16        // nodes per warp tile in mma_pool (m16)

// -------- scratch (device globals: no allocations allowed) --------
__device__ int    g_deg[N_NODES];
__device__ int    g_cur[N_NODES];
__device__ float  g_dis[N_NODES];
__device__ __align__(16) int g_csr[N_NODES * CAP];        // padded to 8-mult with N_NODES
__device__ __align__(16) float g_ps[N_NODES * 4];         // {d*p0, d*p1, d*p2, d}
__device__ __align__(16) __half g_h1[(N_NODES + 1) * 32]; // h1' = d*relu(...); row N_NODES = 0
__device__ __align__(16) __half g_agg2h[N_NODES * 32];    // layer-2 aggregate, fp16
__device__ float  g_pooled[N_GRAPHS * 64];
__device__ int    g_done;

__device__ __forceinline__ void red_add_s32(int* p, int v) {
    asm volatile("red.global.add.s32 [%0], %1;" :: "l"(p), "r"(v) : "memory");
}

// Paired-edge fp16 gather (rows padded to 8-mult with all-zero dummy node).
// Lanes 0-15: even edges, 16-31: odd; each lane one half2 (2 feats). fp32 accum.
__device__ __forceinline__ float gather_sum_h2(const int* __restrict__ csr, int padded,
                                               const __half* __restrict__ tbl, int lane) {
    const int grp = lane >> 4;
    const int sub = lane & 15;
    const __half2* t2 = reinterpret_cast<const __half2*>(tbl);
    float ax0 = 0.f, ay0 = 0.f, ax1 = 0.f, ay1 = 0.f;

#pragma unroll 2
    for (int p = 0; p < padded; p += 8) {
        int4 q0 = __ldg(reinterpret_cast<const int4*>(csr + p));
        int4 q1 = __ldg(reinterpret_cast<const int4*>(csr + p + 4));
        int ra = grp ? q0.y : q0.x;
        int rb = grp ? q0.w : q0.z;
        int rc = grp ? q1.y : q1.x;
        int rd = grp ? q1.w : q1.z;
        float2 fa = __half22float2(__ldg(&t2[ra * 16 + sub]));
        float2 fb = __half22float2(__ldg(&t2[rb * 16 + sub]));
        float2 fc = __half22float2(__ldg(&t2[rc * 16 + sub]));
        float2 fd = __half22float2(__ldg(&t2[rd * 16 + sub]));
        ax0 += fa.x + fb.x;  ay0 += fa.y + fb.y;
        ax1 += fc.x + fd.x;  ay1 += fc.y + fd.y;
    }
    float ax = ax0 + ax1, ay = ay0 + ay1;
    ax += __shfl_xor_sync(0xffffffff, ax, 16);
    ay += __shfl_xor_sync(0xffffffff, ay, 16);
    float vx = __shfl_sync(0xffffffff, ax, lane >> 1);
    float vy = __shfl_sync(0xffffffff, ay, lane >> 1);
    return (lane & 1) ? vy : vx;
}

// -------- init --------
__global__ void k_init() {
    int t = blockIdx.x * blockDim.x + threadIdx.x;
    if (t < N_NODES) { g_deg[t] = 1; g_cur[t] = 0; }
    if (t < N_GRAPHS * 64) reinterpret_cast<int*>(g_pooled)[t] = 0xFF800000;
    if (t < 32) g_h1[N_NODES * 32 + t] = __float2half(0.f);
    if (t == 32) g_done = 0;
}

// -------- build: 8 edges/thread --------
__global__ void k_build(const int4* __restrict__ row4, const int4* __restrict__ col4) {
    int t = blockIdx.x * blockDim.x + threadIdx.x;
    if (t >= N_EDGES / 8) return;
#pragma unroll
    for (int u = 0; u < 2; u++) {
        int4 r = row4[t * 2 + u];
        int4 c = col4[t * 2 + u];
        red_add_s32(&g_deg[r.x], 1);
        red_add_s32(&g_deg[r.y], 1);
        red_add_s32(&g_deg[r.z], 1);
        red_add_s32(&g_deg[r.w], 1);
        int l0 = atomicAdd(&g_cur[c.x], 1);
        int l1 = atomicAdd(&g_cur[c.y], 1);
        int l2 = atomicAdd(&g_cur[c.z], 1);
        int l3 = atomicAdd(&g_cur[c.w], 1);
        if (l0 < CAP) g_csr[c.x * CAP + l0] = r.x;
        if (l1 < CAP) g_csr[c.y * CAP + l1] = r.y;
        if (l2 < CAP) g_csr[c.z * CAP + l2] = r.z;
        if (l3 < CAP) g_csr[c.w * CAP + l3] = r.w;
    }
}

// -------- prep: d = rsqrt(deg); ps = {d*p, d}; pad csr row to 8-mult --------
__global__ void k_prep(const float* __restrict__ pos) {
    int w = (blockIdx.x * blockDim.x + threadIdx.x) >> 5;
    int lane = threadIdx.x & 31;
    if (w >= N_NODES) return;
    float d = rsqrtf((float)g_deg[w]);

    int cnt = min(g_cur[w], CAP);
    int padded = (cnt + 7) & ~7;
    int j = cnt + lane;
    if (lane < 8 && j < padded) g_csr[w * CAP + j] = N_NODES;  // dummy

    if (lane == 0) {
        g_dis[w] = d;
        float p0 = pos[w * 3 + 0], p1 = pos[w * 3 + 1], p2 = pos[w * 3 + 2];
        *reinterpret_cast<float4*>(&g_ps[w * 4]) = make_float4(d * p0, d * p1, d * p2, d);
    }
}

// -------- layer 1: gather 16B ps/edge, shfl-reduce, W1 transform; warp/node --------
__global__ void k_gather1(const float* __restrict__ W1, const float* __restrict__ b1) {
    int i = (blockIdx.x * blockDim.x + threadIdx.x) >> 5;
    int lane = threadIdx.x & 31;
    if (i >= N_NODES) return;
    int cnt = min(g_cur[i], CAP);
    float dc = g_dis[i];

    float a0 = 0.f, a1 = 0.f, a2 = 0.f;
    for (int j = lane; j < cnt; j += 32) {
        int r = __ldg(&g_csr[i * CAP + j]);
        float4 ps = *reinterpret_cast<const float4*>(&g_ps[r * 4]);
        a0 += ps.x; a1 += ps.y; a2 += ps.z;
    }
#pragma unroll
    for (int s = 16; s > 0; s >>= 1) {
        a0 += __shfl_xor_sync(0xffffffff, a0, s);
        a1 += __shfl_xor_sync(0xffffffff, a1, s);
        a2 += __shfl_xor_sync(0xffffffff, a2, s);
    }
    float4 psc = *reinterpret_cast<const float4*>(&g_ps[i * 4]);
    a0 = dc * (a0 + psc.x);
    a1 = dc * (a1 + psc.y);
    a2 = dc * (a2 + psc.z);

    int o = lane;
    float acc = __ldg(&b1[o]) + a0 * __ldg(&W1[o * 3 + 0])
                              + a1 * __ldg(&W1[o * 3 + 1])
                              + a2 * __ldg(&W1[o * 3 + 2]);
    g_h1[i * 32 + o] = __float2half(dc * fmaxf(acc, 0.f));
}

// -------- layer 2 gather only: agg2 (fp16) = d_i * (sum h1'_r + h1'_i) --------
__global__ void __launch_bounds__(256) k_gather2() {
    int warp = (blockIdx.x * blockDim.x + threadIdx.x) >> 5;
    int lane = threadIdx.x & 31;
    int base = warp * NPW;
    if (base >= N_NODES) return;

    for (int t = 0; t < NPW; t += 2) {
        int i0 = base + t;
        int i1 = i0 + 1;
        if (i0 >= N_NODES) break;

        int pad0 = (min(g_cur[i0], CAP) + 7) & ~7;
        float a = __half2float(g_h1[i0 * 32 + lane]);
        a += gather_sum_h2(&g_csr[i0 * CAP], pad0, g_h1, lane);

        float b = 0.f;
        bool v1 = (i1 < N_NODES);
        if (v1) {
            int pad1 = (min(g_cur[i1], CAP) + 7) & ~7;
            b = __half2float(g_h1[i1 * 32 + lane]);
            b += gather_sum_h2(&g_csr[i1 * CAP], pad1, g_h1, lane);
        }
        g_agg2h[i0 * 32 + lane] = __float2half(g_dis[i0] * a);
        if (v1) g_agg2h[i1 * 32 + lane] = __float2half(g_dis[i1] * b);
    }
}

// -------- transform2 (HMMA) + relu + pool + (last block) head --------
// warp tile = 16 nodes (m16), k=32, n=64: 16x mma.m16n8k16
__global__ void __launch_bounds__(256) k_mma_pool(const float* __restrict__ W2,
                                                  const float* __restrict__ b2,
                                                  const int*   __restrict__ batch,
                                                  const float* __restrict__ Wc,
                                                  const float* __restrict__ bc,
                                                  float*       __restrict__ out) {
    __shared__ __align__(16) __half sA[8 * 16 * 40];   // 8 warps x 16 rows x 80B stride
    __shared__ __align__(16) __half sW2[32 * 72];      // [k][n] fp16, stride 144B

    int tid = threadIdx.x;
    int wid = tid >> 5;
    int lane = tid & 31;

    // stage W2^T as fp16: sW2[k*72 + o] = W2[o*32 + k]
    for (int x = tid; x < 32 * 64; x += 256) {
        int k = x >> 6, o = x & 63;
        sW2[k * 72 + o] = __float2half(__ldg(&W2[o * 32 + k]));
    }
    __syncthreads();

    int warp = blockIdx.x * 8 + wid;
    int base = warp * NTILE;

    if (base < N_NODES) {
        // ---- stage A tile (16 nodes x 32 feats fp16) into padded smem ----
        __half* Aw = &sA[wid * 16 * 40];
        const uint4* src = reinterpret_cast<const uint4*>(g_agg2h) + base * 4;
#pragma unroll
        for (int k = 0; k < 2; k++) {
            int c = lane + 32 * k;        // chunk: node c>>2, 16B piece c&3
            uint4 v = __ldg(&src[c]);
            *reinterpret_cast<uint4*>(reinterpret_cast<char*>(Aw) + (c >> 2) * 80 + (c & 3) * 16) = v;
        }
        __syncwarp();

        // ---- A fragments via ldmatrix.x4 (canonical m16k16 idiom) ----
        unsigned a0[4], a1[4];
        {
            unsigned ab = (unsigned)__cvta_generic_to_shared(Aw);
            unsigned addr0 = ab + (lane & 15) * 80 + (lane >> 4) * 16;
            asm volatile("ldmatrix.sync.aligned.m8n8.x4.shared.b16 {%0,%1,%2,%3}, [%4];"
                         : "=r"(a0[0]), "=r"(a0[1]), "=r"(a0[2]), "=r"(a0[3]) : "r"(addr0));
            unsigned addr1 = addr0 + 32;   // k 16..31
            asm volatile("ldmatrix.sync.aligned.m8n8.x4.shared.b16 {%0,%1,%2,%3}, [%4];"
                         : "=r"(a1[0]), "=r"(a1[1]), "=r"(a1[2]), "=r"(a1[3]) : "r"(addr1));
        }

        // ---- 8 n-tiles x 2 k-halves of mma.m16n8k16 ----
        float c[8][4];
#pragma unroll
        for (int n0 = 0; n0 < 8; n0++) { c[n0][0] = c[n0][1] = c[n0][2] = c[n0][3] = 0.f; }

        unsigned wb = (unsigned)__cvta_generic_to_shared(sW2);
#pragma unroll
        for (int n0 = 0; n0 < 8; n0++) {
            unsigned b0, b1;
            unsigned baddr0 = wb + (lane & 15) * 144 + n0 * 16;          // k 0..15
            asm volatile("ldmatrix.sync.aligned.m8n8.x2.trans.shared.b16 {%0,%1}, [%2];"
                         : "=r"(b0), "=r"(b1) : "r"(baddr0));
            asm volatile("mma.sync.aligned.m16n8k16.row.col.f32.f16.f16.f32 "
                         "{%0,%1,%2,%3}, {%4,%5,%6,%7}, {%8,%9}, {%0,%1,%2,%3};"
                         : "+f"(c[n0][0]), "+f"(c[n0][1]), "+f"(c[n0][2]), "+f"(c[n0][3])
                         : "r"(a0[0]), "r"(a0[1]), "r"(a0[2]), "r"(a0[3]), "r"(b0), "r"(b1));
            unsigned baddr1 = wb + (16 + (lane & 15)) * 144 + n0 * 16;   // k 16..31
            asm volatile("ldmatrix.sync.aligned.m8n8.x2.trans.shared.b16 {%0,%1}, [%2];"
                         : "=r"(b0), "=r"(b1) : "r"(baddr1));
            asm volatile("mma.sync.aligned.m16n8k16.row.col.f32.f16.f16.f32 "
                         "{%0,%1,%2,%3}, {%4,%5,%6,%7}, {%8,%9}, {%0,%1,%2,%3};"
                         : "+f"(c[n0][0]), "+f"(c[n0][1]), "+f"(c[n0][2]), "+f"(c[n0][3])
                         : "r"(a1[0]), "r"(a1[1]), "r"(a1[2]), "r"(a1[3]), "r"(b0), "r"(b1));
        }

        // ---- bias + relu in fragments ----
        int q = lane & 3;
#pragma unroll
        for (int n0 = 0; n0 < 8; n0++) {
            float bx = __ldg(&b2[n0 * 8 + q * 2]);
            float by = __ldg(&b2[n0 * 8 + q * 2 + 1]);
            c[n0][0] = fmaxf(c[n0][0] + bx, 0.f);
            c[n0][1] = fmaxf(c[n0][1] + by, 0.f);
            c[n0][2] = fmaxf(c[n0][2] + bx, 0.f);
            c[n0][3] = fmaxf(c[n0][3] + by, 0.f);
        }

        // ---- pool straight from fragments ----
        // rows: lane>>2 (c0,c1) and lane>>2 + 8 (c2,c3). Masking wrong-graph rows
        // with 0 is safe: pooled values are maxima of relu outputs (>= 0).
        int bA = __ldg(&batch[base + (lane >> 2)]);
        int bB = __ldg(&batch[base + 8 + (lane >> 2)]);
        int gfirst = __ldg(&batch[base]);
        int glast  = __ldg(&batch[base + 15]);

        for (int g = gfirst; g <= glast; g++) {
            bool m0 = (bA == g), m1 = (bB == g);
#pragma unroll
            for (int n0 = 0; n0 < 8; n0++) {
                float v0 = fmaxf(m0 ? c[n0][0] : 0.f, m1 ? c[n0][2] : 0.f);
                float v1 = fmaxf(m0 ? c[n0][1] : 0.f, m1 ? c[n0][3] : 0.f);
#pragma unroll
                for (int s = 4; s <= 16; s <<= 1) {
                    v0 = fmaxf(v0, __shfl_xor_sync(0xffffffff, v0, s));
                    v1 = fmaxf(v1, __shfl_xor_sync(0xffffffff, v1, s));
                }
                if (lane < 4) {
                    atomicMax(reinterpret_cast<int*>(&g_pooled[g * 64 + n0 * 8 + lane * 2]),
                              __float_as_int(v0));
                    atomicMax(reinterpret_cast<int*>(&g_pooled[g * 64 + n0 * 8 + lane * 2 + 1]),
                              __float_as_int(v1));
                }
            }
        }
    }

    // ---- last-block head: out = pooled @ Wc^T + bc ----
    __threadfence();
    __shared__ int sLast;
    if (tid == 0) sLast = (atomicAdd(&g_done, 1) == (int)gridDim.x - 1);
    __syncthreads();
    if (sLast) {
        for (int t = tid; t < N_GRAPHS * 2; t += 256) {
            int g = t >> 1;
            int o = t & 1;
            float acc = __ldg(&bc[o]);
#pragma unroll
            for (int k = 0; k < 64; k++)
                acc = fmaf(__ldcg(&g_pooled[g * 64 + k]), __ldg(&Wc[o * 64 + k]), acc);
            out[t] = acc;
        }
    }
}

extern "C" void kernel_launch(void* const* d_in, const int* in_sizes, int n_in,
                              void* d_out, int out_size) {
    const float* pos  = (const float*)d_in[0];
    const int*   eidx = (const int*)  d_in[1];
    const int*   bat  = (const int*)  d_in[2];
    const float* W1   = (const float*)d_in[3];
    const float* b1   = (const float*)d_in[4];
    const float* W2   = (const float*)d_in[5];
    const float* b2   = (const float*)d_in[6];
    const float* Wc   = (const float*)d_in[7];
    const float* bc   = (const float*)d_in[8];
    float* out = (float*)d_out;

    const int* row = eidx;             // edge_index[0]
    const int* col = eidx + N_EDGES;   // edge_index[1]

    const int TB = 256;

    k_init <<<(N_NODES + TB - 1) / TB, TB>>>();
    k_build<<<(N_EDGES / 8 + TB - 1) / TB, TB>>>((const int4*)row, (const int4*)col);
    k_prep <<<(N_NODES * 32 + TB - 1) / TB, TB>>>(pos);
    k_gather1<<<(N_NODES * 32 + TB - 1) / TB, TB>>>(W1, b1);
    {
        int warps = (N_NODES + NPW - 1) / NPW;
        int blocks = (warps * 32 + TB - 1) / TB;
        k_gather2<<<blocks, TB>>>();
    }
    {
        int warps = (N_NODES + NTILE - 1) / NTILE;   // 6250
        int blocks = (warps + 7) / 8;                // 782
        k_mma_pool<<<blocks, TB>>>(W2, b2, bat, Wc, bc, out);
    }
}

// round 13
// speedup vs baseline: 1.4204x; 1.1588x over previous
#include <cuda_runtime.h>
#include <cuda_fp16.h>
#include <math.h>

#define N_NODES  100000
#define N_EDGES  3200000
#define N_GRAPHS 256
#define CAP      96        // P(in-degree >= 96) ~ e^-41 per node; multiple of 8
#define NPW      16        // nodes per warp in gather2
#define NTILE    16        // nodes per warp tile in mma_pool (m16)

// -------- scratch (device globals: no allocations allowed) --------
__device__ int    g_deg[N_NODES];
__device__ int    g_cur[N_NODES];
__device__ float  g_dis[N_NODES];
__device__ __align__(16) int g_csr[N_NODES * CAP];        // padded to 8-mult with N_NODES
__device__ __align__(16) float g_ps[N_NODES * 4];         // {d*p0, d*p1, d*p2, d}
__device__ __align__(16) __half g_h1[(N_NODES + 1) * 32]; // h1' = d*relu(...); row N_NODES = 0
__device__ __align__(16) __half g_agg2h[N_NODES * 32];    // layer-2 aggregate, fp16
__device__ float  g_pooled[N_GRAPHS * 64];
__device__ int    g_done;

__device__ __forceinline__ void red_add_s32(int* p, int v) {
    asm volatile("red.global.add.s32 [%0], %1;" :: "l"(p), "r"(v) : "memory");
}

// -------- init --------
__global__ void k_init() {
    int t = blockIdx.x * blockDim.x + threadIdx.x;
    if (t < N_NODES) { g_deg[t] = 1; g_cur[t] = 0; }
    if (t < N_GRAPHS * 64) reinterpret_cast<int*>(g_pooled)[t] = 0xFF800000;
    if (t < 32) g_h1[N_NODES * 32 + t] = __float2half(0.f);
    if (t == 32) g_done = 0;
}

// -------- build: 8 edges/thread --------
__global__ void k_build(const int4* __restrict__ row4, const int4* __restrict__ col4) {
    int t = blockIdx.x * blockDim.x + threadIdx.x;
    if (t >= N_EDGES / 8) return;
#pragma unroll
    for (int u = 0; u < 2; u++) {
        int4 r = row4[t * 2 + u];
        int4 c = col4[t * 2 + u];
        red_add_s32(&g_deg[r.x], 1);
        red_add_s32(&g_deg[r.y], 1);
        red_add_s32(&g_deg[r.z], 1);
        red_add_s32(&g_deg[r.w], 1);
        int l0 = atomicAdd(&g_cur[c.x], 1);
        int l1 = atomicAdd(&g_cur[c.y], 1);
        int l2 = atomicAdd(&g_cur[c.z], 1);
        int l3 = atomicAdd(&g_cur[c.w], 1);
        if (l0 < CAP) g_csr[c.x * CAP + l0] = r.x;
        if (l1 < CAP) g_csr[c.y * CAP + l1] = r.y;
        if (l2 < CAP) g_csr[c.z * CAP + l2] = r.z;
        if (l3 < CAP) g_csr[c.w * CAP + l3] = r.w;
    }
}

// -------- prep (thread per node): d, ps, csr row pad to 8-mult --------
__global__ void k_prep(const float* __restrict__ pos) {
    int w = blockIdx.x * blockDim.x + threadIdx.x;
    if (w >= N_NODES) return;
    float d = rsqrtf((float)g_deg[w]);
    g_dis[w] = d;

    int cnt = min(g_cur[w], CAP);
    int padded = (cnt + 7) & ~7;
    for (int j = cnt; j < padded; j++) g_csr[w * CAP + j] = N_NODES;  // dummy

    float p0 = pos[w * 3 + 0], p1 = pos[w * 3 + 1], p2 = pos[w * 3 + 2];
    *reinterpret_cast<float4*>(&g_ps[w * 4]) = make_float4(d * p0, d * p1, d * p2, d);
}

// -------- layer 1: gather 16B ps/edge, shfl-reduce, W1 transform; warp/node --------
__global__ void k_gather1(const float* __restrict__ W1, const float* __restrict__ b1) {
    int i = (blockIdx.x * blockDim.x + threadIdx.x) >> 5;
    int lane = threadIdx.x & 31;
    if (i >= N_NODES) return;
    int cnt = min(g_cur[i], CAP);
    float dc = g_dis[i];

    float a0 = 0.f, a1 = 0.f, a2 = 0.f;
    for (int j = lane; j < cnt; j += 32) {
        int r = __ldg(&g_csr[i * CAP + j]);
        float4 ps = *reinterpret_cast<const float4*>(&g_ps[r * 4]);
        a0 += ps.x; a1 += ps.y; a2 += ps.z;
    }
#pragma unroll
    for (int s = 16; s > 0; s >>= 1) {
        a0 += __shfl_xor_sync(0xffffffff, a0, s);
        a1 += __shfl_xor_sync(0xffffffff, a1, s);
        a2 += __shfl_xor_sync(0xffffffff, a2, s);
    }
    float4 psc = *reinterpret_cast<const float4*>(&g_ps[i * 4]);
    a0 = dc * (a0 + psc.x);
    a1 = dc * (a1 + psc.y);
    a2 = dc * (a2 + psc.z);

    int o = lane;
    float acc = __ldg(&b1[o]) + a0 * __ldg(&W1[o * 3 + 0])
                              + a1 * __ldg(&W1[o * 3 + 1])
                              + a2 * __ldg(&W1[o * 3 + 2]);
    g_h1[i * 32 + o] = __float2half(dc * fmaxf(acc, 0.f));
}

// -------- layer 2 gather: 4 lanes/edge, half2 accum (flush every 16 edges) --------
__global__ void __launch_bounds__(256) k_gather2() {
    int warp = (blockIdx.x * blockDim.x + threadIdx.x) >> 5;
    int lane = threadIdx.x & 31;
    int grp  = lane >> 3;       // edge slot 0..3 within sub-iter
    int q    = lane & 7;        // uint2 slot: features q*4 .. q*4+3
    int base = warp * NPW;
    if (base >= N_NODES) return;

    for (int t = 0; t < NPW; t++) {
        int i = base + t;
        if (i >= N_NODES) break;
        int padded = (min(g_cur[i], CAP) + 7) & ~7;
        const int* csr = &g_csr[i * CAP];

        float f0 = 0.f, f1 = 0.f, f2 = 0.f, f3 = 0.f;

        int p = 0;
        // full 16-edge superchunks: each h2 accumulator sees exactly 4 adds
        for (; p + 16 <= padded; p += 16) {
            __half2 h0 = __float2half2_rn(0.f), h1v = __float2half2_rn(0.f);
#pragma unroll
            for (int u = 0; u < 4; u++) {
                int r = __ldg(&csr[p + u * 4 + grp]);
                uint2 v = __ldg(reinterpret_cast<const uint2*>(g_h1 + r * 32) + q);
                h0  = __hadd2(h0,  *reinterpret_cast<__half2*>(&v.x));
                h1v = __hadd2(h1v, *reinterpret_cast<__half2*>(&v.y));
            }
            float2 fa = __half22float2(h0);
            float2 fb = __half22float2(h1v);
            f0 += fa.x; f1 += fa.y; f2 += fb.x; f3 += fb.y;
        }
        // remainder: padded mult of 8, consumed mult of 16 -> 0 or 8 edges left
        if (p < padded) {
            __half2 h0 = __float2half2_rn(0.f), h1v = __float2half2_rn(0.f);
#pragma unroll
            for (int u = 0; u < 2; u++) {
                int r = __ldg(&csr[p + u * 4 + grp]);
                uint2 v = __ldg(reinterpret_cast<const uint2*>(g_h1 + r * 32) + q);
                h0  = __hadd2(h0,  *reinterpret_cast<__half2*>(&v.x));
                h1v = __hadd2(h1v, *reinterpret_cast<__half2*>(&v.y));
            }
            float2 fa = __half22float2(h0);
            float2 fb = __half22float2(h1v);
            f0 += fa.x; f1 += fa.y; f2 += fb.x; f3 += fb.y;
        }

        // reduce across the 4 edge-groups (lanes q, q+8, q+16, q+24)
#pragma unroll
        for (int s = 8; s <= 16; s <<= 1) {
            f0 += __shfl_xor_sync(0xffffffff, f0, s);
            f1 += __shfl_xor_sync(0xffffffff, f1, s);
            f2 += __shfl_xor_sync(0xffffffff, f2, s);
            f3 += __shfl_xor_sync(0xffffffff, f3, s);
        }

        // self loop AFTER the reduction (added exactly once per feature)
        {
            uint2 v = __ldg(reinterpret_cast<const uint2*>(g_h1 + i * 32) + q);
            float2 fa = __half22float2(*reinterpret_cast<__half2*>(&v.x));
            float2 fb = __half22float2(*reinterpret_cast<__half2*>(&v.y));
            f0 += fa.x; f1 += fa.y; f2 += fb.x; f3 += fb.y;
        }

        if (lane < 8) {
            float d = g_dis[i];
            __half2 o0 = __floats2half2_rn(d * f0, d * f1);
            __half2 o1 = __floats2half2_rn(d * f2, d * f3);
            uint2 w;
            w.x = *reinterpret_cast<unsigned*>(&o0);
            w.y = *reinterpret_cast<unsigned*>(&o1);
            *(reinterpret_cast<uint2*>(g_agg2h + i * 32) + q) = w;
        }
    }
}

// -------- transform2 (HMMA) + relu + pool + (last block) head --------
__global__ void __launch_bounds__(256) k_mma_pool(const float* __restrict__ W2,
                                                  const float* __restrict__ b2,
                                                  const int*   __restrict__ batch,
                                                  const float* __restrict__ Wc,
                                                  const float* __restrict__ bc,
                                                  float*       __restrict__ out) {
    __shared__ __align__(16) __half sA[8 * 16 * 40];   // 8 warps x 16 rows x 80B stride
    __shared__ __align__(16) __half sW2[32 * 72];      // [k][n] fp16, stride 144B

    int tid = threadIdx.x;
    int wid = tid >> 5;
    int lane = tid & 31;

    for (int x = tid; x < 32 * 64; x += 256) {
        int k = x >> 6, o = x & 63;
        sW2[k * 72 + o] = __float2half(__ldg(&W2[o * 32 + k]));
    }
    __syncthreads();

    int warp = blockIdx.x * 8 + wid;
    int base = warp * NTILE;

    if (base < N_NODES) {
        __half* Aw = &sA[wid * 16 * 40];
        const uint4* src = reinterpret_cast<const uint4*>(g_agg2h) + base * 4;
#pragma unroll
        for (int k = 0; k < 2; k++) {
            int c = lane + 32 * k;
            uint4 v = __ldg(&src[c]);
            *reinterpret_cast<uint4*>(reinterpret_cast<char*>(Aw) + (c >> 2) * 80 + (c & 3) * 16) = v;
        }
        __syncwarp();

        unsigned a0[4], a1[4];
        {
            unsigned ab = (unsigned)__cvta_generic_to_shared(Aw);
            unsigned addr0 = ab + (lane & 15) * 80 + (lane >> 4) * 16;
            asm volatile("ldmatrix.sync.aligned.m8n8.x4.shared.b16 {%0,%1,%2,%3}, [%4];"
                         : "=r"(a0[0]), "=r"(a0[1]), "=r"(a0[2]), "=r"(a0[3]) : "r"(addr0));
            unsigned addr1 = addr0 + 32;
            asm volatile("ldmatrix.sync.aligned.m8n8.x4.shared.b16 {%0,%1,%2,%3}, [%4];"
                         : "=r"(a1[0]), "=r"(a1[1]), "=r"(a1[2]), "=r"(a1[3]) : "r"(addr1));
        }

        float c[8][4];
#pragma unroll
        for (int n0 = 0; n0 < 8; n0++) { c[n0][0] = c[n0][1] = c[n0][2] = c[n0][3] = 0.f; }

        unsigned wb = (unsigned)__cvta_generic_to_shared(sW2);
#pragma unroll
        for (int n0 = 0; n0 < 8; n0++) {
            unsigned b0, b1;
            unsigned baddr0 = wb + (lane & 15) * 144 + n0 * 16;
            asm volatile("ldmatrix.sync.aligned.m8n8.x2.trans.shared.b16 {%0,%1}, [%2];"
                         : "=r"(b0), "=r"(b1) : "r"(baddr0));
            asm volatile("mma.sync.aligned.m16n8k16.row.col.f32.f16.f16.f32 "
                         "{%0,%1,%2,%3}, {%4,%5,%6,%7}, {%8,%9}, {%0,%1,%2,%3};"
                         : "+f"(c[n0][0]), "+f"(c[n0][1]), "+f"(c[n0][2]), "+f"(c[n0][3])
                         : "r"(a0[0]), "r"(a0[1]), "r"(a0[2]), "r"(a0[3]), "r"(b0), "r"(b1));
            unsigned baddr1 = wb + (16 + (lane & 15)) * 144 + n0 * 16;
            asm volatile("ldmatrix.sync.aligned.m8n8.x2.trans.shared.b16 {%0,%1}, [%2];"
                         : "=r"(b0), "=r"(b1) : "r"(baddr1));
            asm volatile("mma.sync.aligned.m16n8k16.row.col.f32.f16.f16.f32 "
                         "{%0,%1,%2,%3}, {%4,%5,%6,%7}, {%8,%9}, {%0,%1,%2,%3};"
                         : "+f"(c[n0][0]), "+f"(c[n0][1]), "+f"(c[n0][2]), "+f"(c[n0][3])
                         : "r"(a1[0]), "r"(a1[1]), "r"(a1[2]), "r"(a1[3]), "r"(b0), "r"(b1));
        }

        int q = lane & 3;
#pragma unroll
        for (int n0 = 0; n0 < 8; n0++) {
            float bx = __ldg(&b2[n0 * 8 + q * 2]);
            float by = __ldg(&b2[n0 * 8 + q * 2 + 1]);
            c[n0][0] = fmaxf(c[n0][0] + bx, 0.f);
            c[n0][1] = fmaxf(c[n0][1] + by, 0.f);
            c[n0][2] = fmaxf(c[n0][2] + bx, 0.f);
            c[n0][3] = fmaxf(c[n0][3] + by, 0.f);
        }

        int bA = __ldg(&batch[base + (lane >> 2)]);
        int bB = __ldg(&batch[base + 8 + (lane >> 2)]);
        int gfirst = __ldg(&batch[base]);
        int glast  = __ldg(&batch[base + 15]);

        for (int g = gfirst; g <= glast; g++) {
            bool m0 = (bA == g), m1 = (bB == g);
#pragma unroll
            for (int n0 = 0; n0 < 8; n0++) {
                float v0 = fmaxf(m0 ? c[n0][0] : 0.f, m1 ? c[n0][2] : 0.f);
                float v1 = fmaxf(m0 ? c[n0][1] : 0.f, m1 ? c[n0][3] : 0.f);
#pragma unroll
                for (int s = 4; s <= 16; s <<= 1) {
                    v0 = fmaxf(v0, __shfl_xor_sync(0xffffffff, v0, s));
                    v1 = fmaxf(v1, __shfl_xor_sync(0xffffffff, v1, s));
                }
                if (lane < 4) {
                    atomicMax(reinterpret_cast<int*>(&g_pooled[g * 64 + n0 * 8 + lane * 2]),
                              __float_as_int(v0));
                    atomicMax(reinterpret_cast<int*>(&g_pooled[g * 64 + n0 * 8 + lane * 2 + 1]),
                              __float_as_int(v1));
                }
            }
        }
    }

    // ---- last-block head ----
    __threadfence();
    __shared__ int sLast;
    if (tid == 0) sLast = (atomicAdd(&g_done, 1) == (int)gridDim.x - 1);
    __syncthreads();
    if (sLast) {
        for (int t = tid; t < N_GRAPHS * 2; t += 256) {
            int g = t >> 1;
            int o = t & 1;
            float acc = __ldg(&bc[o]);
#pragma unroll
            for (int k = 0; k < 64; k++)
                acc = fmaf(__ldcg(&g_pooled[g * 64 + k]), __ldg(&Wc[o * 64 + k]), acc);
            out[t] = acc;
        }
    }
}

extern "C" void kernel_launch(void* const* d_in, const int* in_sizes, int n_in,
                              void* d_out, int out_size) {
    const float* pos  = (const float*)d_in[0];
    const int*   eidx = (const int*)  d_in[1];
    const int*   bat  = (const int*)  d_in[2];
    const float* W1   = (const float*)d_in[3];
    const float* b1   = (const float*)d_in[4];
    const float* W2   = (const float*)d_in[5];
    const float* b2   = (const float*)d_in[6];
    const float* Wc   = (const float*)d_in[7];
    const float* bc   = (const float*)d_in[8];
    float* out = (float*)d_out;

    const int* row = eidx;             // edge_index[0]
    const int* col = eidx + N_EDGES;   // edge_index[1]

    const int TB = 256;

    k_init <<<(N_NODES + TB - 1) / TB, TB>>>();
    k_build<<<(N_EDGES / 8 + TB - 1) / TB, TB>>>((const int4*)row, (const int4*)col);
    k_prep <<<(N_NODES + TB - 1) / TB, TB>>>(pos);
    k_gather1<<<(N_NODES * 32 + TB - 1) / TB, TB>>>(W1, b1);
    {
        int warps = (N_NODES + NPW - 1) / NPW;
        int blocks = (warps * 32 + TB - 1) / TB;
        k_gather2<<<blocks, TB>>>();
    }
    {
        int warps = (N_NODES + NTILE - 1) / NTILE;   // 6250
        int blocks = (warps + 7) / 8;                // 782
        k_mma_pool<<<blocks, TB>>>(W2, b2, bat, Wc, bc, out);
    }
}

// round 14
// speedup vs baseline: 1.4220x; 1.0011x over previous
#include <cuda_runtime.h>
#include <cuda_fp16.h>
#include <math.h>

#define N_NODES  100000
#define N_EDGES  3200000
#define N_GRAPHS 256
#define CAP      96        // P(in-degree >= 96) ~ e^-41 per node; multiple of 8
#define NPW      16        // nodes per warp in gather2
#define NTILE    16        // nodes per warp tile in mma_pool (m16)

// -------- scratch (device globals: zero-initialized at module load) --------
// State contract: every kernel_launch leaves deg/cur zeroed, pooled = -inf bits,
// done = 0 (reset in k_mma_pool epilogue), so graph replays are deterministic.
__device__ int    g_deg[N_NODES];                          // starts 0; deg = this + 1
__device__ int    g_cur[N_NODES];
__device__ float  g_dis[N_NODES];
__device__ __align__(16) int g_csr[N_NODES * CAP];         // padded to 8-mult with N_NODES
__device__ __align__(16) float g_ps[(N_NODES + 1) * 4];    // {d*p, d}; row N_NODES stays 0
__device__ __align__(16) __half g_h1[(N_NODES + 1) * 32];  // h1'; row N_NODES stays 0
__device__ __align__(16) __half g_agg2h[N_NODES * 32];     // layer-2 aggregate, fp16
__device__ float  g_pooled[N_GRAPHS * 64];                 // kept at -inf bits between runs
__device__ int    g_pooled_virgin;                         // 0 on first run
__device__ int    g_done;

__device__ __forceinline__ void red_add_s32(int* p, int v) {
    asm volatile("red.global.add.s32 [%0], %1;" :: "l"(p), "r"(v) : "memory");
}

// -------- build: 8 edges/thread; also first-run pooled init --------
__global__ void k_build(const int4* __restrict__ row4, const int4* __restrict__ col4) {
    int t = blockIdx.x * blockDim.x + threadIdx.x;
    // first-run-only: pooled must be -inf bits (globals start at 0.0f).
    // Deterministic: every launch executes this same code; after run 1 the
    // epilogue maintains the -inf invariant, and virgin flag makes this a no-op
    // only via the same branch shape (stores are idempotent -inf writes on run 1).
    if (t < N_GRAPHS * 64) {
        if (g_pooled_virgin == 0)
            reinterpret_cast<int*>(g_pooled)[t] = 0xFF800000;
    }
    if (t >= N_EDGES / 8) return;
#pragma unroll
    for (int u = 0; u < 2; u++) {
        int4 r = row4[t * 2 + u];
        int4 c = col4[t * 2 + u];
        red_add_s32(&g_deg[r.x], 1);
        red_add_s32(&g_deg[r.y], 1);
        red_add_s32(&g_deg[r.z], 1);
        red_add_s32(&g_deg[r.w], 1);
        int l0 = atomicAdd(&g_cur[c.x], 1);
        int l1 = atomicAdd(&g_cur[c.y], 1);
        int l2 = atomicAdd(&g_cur[c.z], 1);
        int l3 = atomicAdd(&g_cur[c.w], 1);
        if (l0 < CAP) g_csr[c.x * CAP + l0] = r.x;
        if (l1 < CAP) g_csr[c.y * CAP + l1] = r.y;
        if (l2 < CAP) g_csr[c.z * CAP + l2] = r.z;
        if (l3 < CAP) g_csr[c.w * CAP + l3] = r.w;
    }
}

// -------- prep (thread per node): d = rsqrt(deg+1), ps, csr pad to 8-mult --------
__global__ void k_prep(const float* __restrict__ pos) {
    int w = blockIdx.x * blockDim.x + threadIdx.x;
    if (w >= N_NODES) return;
    float d = rsqrtf((float)(g_deg[w] + 1));       // +1: self loop
    g_dis[w] = d;

    int cnt = min(g_cur[w], CAP);
    int padded = (cnt + 7) & ~7;
    for (int j = cnt; j < padded; j++) g_csr[w * CAP + j] = N_NODES;  // dummy

    float p0 = pos[w * 3 + 0], p1 = pos[w * 3 + 1], p2 = pos[w * 3 + 2];
    *reinterpret_cast<float4*>(&g_ps[w * 4]) = make_float4(d * p0, d * p1, d * p2, d);
}

// -------- layer 1: 2 nodes/warp interleaved (MLP=2), branchless dummy loads --------
__global__ void k_gather1(const float* __restrict__ W1, const float* __restrict__ b1) {
    int w = (blockIdx.x * blockDim.x + threadIdx.x) >> 5;
    int lane = threadIdx.x & 31;
    int i0 = w * 2;
    if (i0 >= N_NODES) return;
    int i1 = i0 + 1;
    bool v1 = (i1 < N_NODES);

    int cnt0 = min(g_cur[i0], CAP);
    int cnt1 = v1 ? min(g_cur[i1], CAP) : 0;
    int mx = max(cnt0, cnt1);
    const int* csr0 = &g_csr[i0 * CAP];
    const int* csr1 = &g_csr[i1 * CAP];            // deref guarded by cnt1

    float a0 = 0.f, a1 = 0.f, a2 = 0.f;
    float c0 = 0.f, c1 = 0.f, c2 = 0.f;
    for (int j = lane; j < mx; j += 32) {
        int r0 = (j < cnt0) ? __ldg(&csr0[j]) : N_NODES;
        int r1 = (j < cnt1) ? __ldg(&csr1[j]) : N_NODES;
        float4 p0 = *reinterpret_cast<const float4*>(&g_ps[r0 * 4]);  // dummy row = 0
        float4 p1 = *reinterpret_cast<const float4*>(&g_ps[r1 * 4]);
        a0 += p0.x; a1 += p0.y; a2 += p0.z;
        c0 += p1.x; c1 += p1.y; c2 += p1.z;
    }
#pragma unroll
    for (int s = 16; s > 0; s >>= 1) {
        a0 += __shfl_xor_sync(0xffffffff, a0, s);
        a1 += __shfl_xor_sync(0xffffffff, a1, s);
        a2 += __shfl_xor_sync(0xffffffff, a2, s);
        c0 += __shfl_xor_sync(0xffffffff, c0, s);
        c1 += __shfl_xor_sync(0xffffffff, c1, s);
        c2 += __shfl_xor_sync(0xffffffff, c2, s);
    }

    int o = lane;
    float w0 = __ldg(&W1[o * 3 + 0]);
    float w1v = __ldg(&W1[o * 3 + 1]);
    float w2v = __ldg(&W1[o * 3 + 2]);
    float bo = __ldg(&b1[o]);

    {
        float dc = g_dis[i0];
        float4 psc = *reinterpret_cast<const float4*>(&g_ps[i0 * 4]);
        float x0 = dc * (a0 + psc.x);
        float x1 = dc * (a1 + psc.y);
        float x2 = dc * (a2 + psc.z);
        float acc = bo + x0 * w0 + x1 * w1v + x2 * w2v;
        g_h1[i0 * 32 + o] = __float2half(dc * fmaxf(acc, 0.f));
    }
    if (v1) {
        float dc = g_dis[i1];
        float4 psc = *reinterpret_cast<const float4*>(&g_ps[i1 * 4]);
        float x0 = dc * (c0 + psc.x);
        float x1 = dc * (c1 + psc.y);
        float x2 = dc * (c2 + psc.z);
        float acc = bo + x0 * w0 + x1 * w1v + x2 * w2v;
        g_h1[i1 * 32 + o] = __float2half(dc * fmaxf(acc, 0.f));
    }
}

// -------- layer 2 gather: 4 lanes/edge, half2 accum (flush every 16 edges) --------
__global__ void __launch_bounds__(256) k_gather2() {
    int warp = (blockIdx.x * blockDim.x + threadIdx.x) >> 5;
    int lane = threadIdx.x & 31;
    int grp  = lane >> 3;
    int q    = lane & 7;
    int base = warp * NPW;
    if (base >= N_NODES) return;

    for (int t = 0; t < NPW; t++) {
        int i = base + t;
        if (i >= N_NODES) break;
        int padded = (min(g_cur[i], CAP) + 7) & ~7;
        const int* csr = &g_csr[i * CAP];

        float f0 = 0.f, f1 = 0.f, f2 = 0.f, f3 = 0.f;

        int p = 0;
        for (; p + 16 <= padded; p += 16) {
            __half2 h0 = __float2half2_rn(0.f), h1v = __float2half2_rn(0.f);
#pragma unroll
            for (int u = 0; u < 4; u++) {
                int r = __ldg(&csr[p + u * 4 + grp]);
                uint2 v = __ldg(reinterpret_cast<const uint2*>(g_h1 + r * 32) + q);
                h0  = __hadd2(h0,  *reinterpret_cast<__half2*>(&v.x));
                h1v = __hadd2(h1v, *reinterpret_cast<__half2*>(&v.y));
            }
            float2 fa = __half22float2(h0);
            float2 fb = __half22float2(h1v);
            f0 += fa.x; f1 += fa.y; f2 += fb.x; f3 += fb.y;
        }
        if (p < padded) {
            __half2 h0 = __float2half2_rn(0.f), h1v = __float2half2_rn(0.f);
#pragma unroll
            for (int u = 0; u < 2; u++) {
                int r = __ldg(&csr[p + u * 4 + grp]);
                uint2 v = __ldg(reinterpret_cast<const uint2*>(g_h1 + r * 32) + q);
                h0  = __hadd2(h0,  *reinterpret_cast<__half2*>(&v.x));
                h1v = __hadd2(h1v, *reinterpret_cast<__half2*>(&v.y));
            }
            float2 fa = __half22float2(h0);
            float2 fb = __half22float2(h1v);
            f0 += fa.x; f1 += fa.y; f2 += fb.x; f3 += fb.y;
        }

#pragma unroll
        for (int s = 8; s <= 16; s <<= 1) {
            f0 += __shfl_xor_sync(0xffffffff, f0, s);
            f1 += __shfl_xor_sync(0xffffffff, f1, s);
            f2 += __shfl_xor_sync(0xffffffff, f2, s);
            f3 += __shfl_xor_sync(0xffffffff, f3, s);
        }

        // self loop AFTER the reduction (exactly once per feature)
        {
            uint2 v = __ldg(reinterpret_cast<const uint2*>(g_h1 + i * 32) + q);
            float2 fa = __half22float2(*reinterpret_cast<__half2*>(&v.x));
            float2 fb = __half22float2(*reinterpret_cast<__half2*>(&v.y));
            f0 += fa.x; f1 += fa.y; f2 += fb.x; f3 += fb.y;
        }

        if (lane < 8) {
            float d = g_dis[i];
            __half2 o0 = __floats2half2_rn(d * f0, d * f1);
            __half2 o1 = __floats2half2_rn(d * f2, d * f3);
            uint2 w;
            w.x = *reinterpret_cast<unsigned*>(&o0);
            w.y = *reinterpret_cast<unsigned*>(&o1);
            *(reinterpret_cast<uint2*>(g_agg2h + i * 32) + q) = w;
        }
    }
}

// -------- transform2 (HMMA) + relu + pool + head + state reset --------
__global__ void __launch_bounds__(256) k_mma_pool(const float* __restrict__ W2,
                                                  const float* __restrict__ b2,
                                                  const int*   __restrict__ batch,
                                                  const float* __restrict__ Wc,
                                                  const float* __restrict__ bc,
                                                  float*       __restrict__ out) {
    __shared__ __align__(16) __half sA[8 * 16 * 40];
    __shared__ __align__(16) __half sW2[32 * 72];

    int tid = threadIdx.x;
    int wid = tid >> 5;
    int lane = tid & 31;

    for (int x = tid; x < 32 * 64; x += 256) {
        int k = x >> 6, o = x & 63;
        sW2[k * 72 + o] = __float2half(__ldg(&W2[o * 32 + k]));
    }
    __syncthreads();

    int warp = blockIdx.x * 8 + wid;
    int base = warp * NTILE;

    if (base < N_NODES) {
        __half* Aw = &sA[wid * 16 * 40];
        const uint4* src = reinterpret_cast<const uint4*>(g_agg2h) + base * 4;
#pragma unroll
        for (int k = 0; k < 2; k++) {
            int c = lane + 32 * k;
            uint4 v = __ldg(&src[c]);
            *reinterpret_cast<uint4*>(reinterpret_cast<char*>(Aw) + (c >> 2) * 80 + (c & 3) * 16) = v;
        }
        __syncwarp();

        unsigned a0[4], a1[4];
        {
            unsigned ab = (unsigned)__cvta_generic_to_shared(Aw);
            unsigned addr0 = ab + (lane & 15) * 80 + (lane >> 4) * 16;
            asm volatile("ldmatrix.sync.aligned.m8n8.x4.shared.b16 {%0,%1,%2,%3}, [%4];"
                         : "=r"(a0[0]), "=r"(a0[1]), "=r"(a0[2]), "=r"(a0[3]) : "r"(addr0));
            unsigned addr1 = addr0 + 32;
            asm volatile("ldmatrix.sync.aligned.m8n8.x4.shared.b16 {%0,%1,%2,%3}, [%4];"
                         : "=r"(a1[0]), "=r"(a1[1]), "=r"(a1[2]), "=r"(a1[3]) : "r"(addr1));
        }

        float c[8][4];
#pragma unroll
        for (int n0 = 0; n0 < 8; n0++) { c[n0][0] = c[n0][1] = c[n0][2] = c[n0][3] = 0.f; }

        unsigned wb = (unsigned)__cvta_generic_to_shared(sW2);
#pragma unroll
        for (int n0 = 0; n0 < 8; n0++) {
            unsigned b0, b1;
            unsigned baddr0 = wb + (lane & 15) * 144 + n0 * 16;
            asm volatile("ldmatrix.sync.aligned.m8n8.x2.trans.shared.b16 {%0,%1}, [%2];"
                         : "=r"(b0), "=r"(b1) : "r"(baddr0));
            asm volatile("mma.sync.aligned.m16n8k16.row.col.f32.f16.f16.f32 "
                         "{%0,%1,%2,%3}, {%4,%5,%6,%7}, {%8,%9}, {%0,%1,%2,%3};"
                         : "+f"(c[n0][0]), "+f"(c[n0][1]), "+f"(c[n0][2]), "+f"(c[n0][3])
                         : "r"(a0[0]), "r"(a0[1]), "r"(a0[2]), "r"(a0[3]), "r"(b0), "r"(b1));
            unsigned baddr1 = wb + (16 + (lane & 15)) * 144 + n0 * 16;
            asm volatile("ldmatrix.sync.aligned.m8n8.x2.trans.shared.b16 {%0,%1}, [%2];"
                         : "=r"(b0), "=r"(b1) : "r"(baddr1));
            asm volatile("mma.sync.aligned.m16n8k16.row.col.f32.f16.f16.f32 "
                         "{%0,%1,%2,%3}, {%4,%5,%6,%7}, {%8,%9}, {%0,%1,%2,%3};"
                         : "+f"(c[n0][0]), "+f"(c[n0][1]), "+f"(c[n0][2]), "+f"(c[n0][3])
                         : "r"(a1[0]), "r"(a1[1]), "r"(a1[2]), "r"(a1[3]), "r"(b0), "r"(b1));
        }

        int q = lane & 3;
#pragma unroll
        for (int n0 = 0; n0 < 8; n0++) {
            float bx = __ldg(&b2[n0 * 8 + q * 2]);
            float by = __ldg(&b2[n0 * 8 + q * 2 + 1]);
            c[n0][0] = fmaxf(c[n0][0] + bx, 0.f);
            c[n0][1] = fmaxf(c[n0][1] + by, 0.f);
            c[n0][2] = fmaxf(c[n0][2] + bx, 0.f);
            c[n0][3] = fmaxf(c[n0][3] + by, 0.f);
        }

        int bA = __ldg(&batch[base + (lane >> 2)]);
        int bB = __ldg(&batch[base + 8 + (lane >> 2)]);
        int gfirst = __ldg(&batch[base]);
        int glast  = __ldg(&batch[base + 15]);

        for (int g = gfirst; g <= glast; g++) {
            bool m0 = (bA == g), m1 = (bB == g);
#pragma unroll
            for (int n0 = 0; n0 < 8; n0++) {
                float v0 = fmaxf(m0 ? c[n0][0] : 0.f, m1 ? c[n0][2] : 0.f);
                float v1 = fmaxf(m0 ? c[n0][1] : 0.f, m1 ? c[n0][3] : 0.f);
#pragma unroll
                for (int s = 4; s <= 16; s <<= 1) {
                    v0 = fmaxf(v0, __shfl_xor_sync(0xffffffff, v0, s));
                    v1 = fmaxf(v1, __shfl_xor_sync(0xffffffff, v1, s));
                }
                if (lane < 4) {
                    atomicMax(reinterpret_cast<int*>(&g_pooled[g * 64 + n0 * 8 + lane * 2]),
                              __float_as_int(v0));
                    atomicMax(reinterpret_cast<int*>(&g_pooled[g * 64 + n0 * 8 + lane * 2 + 1]),
                              __float_as_int(v1));
                }
            }
        }
    }

    // ---- state reset for next launch: deg/cur back to 0 ----
    for (int j = blockIdx.x * 256 + tid; j < N_NODES; j += gridDim.x * 256) {
        g_deg[j] = 0;
        g_cur[j] = 0;
    }

    // ---- last-block head + pooled/done reset ----
    __threadfence();
    __shared__ int sLast;
    if (tid == 0) sLast = (atomicAdd(&g_done, 1) == (int)gridDim.x - 1);
    __syncthreads();
    if (sLast) {
        for (int t = tid; t < N_GRAPHS * 2; t += 256) {
            int g = t >> 1;
            int o = t & 1;
            float acc = __ldg(&bc[o]);
#pragma unroll
            for (int k = 0; k < 64; k++)
                acc = fmaf(__ldcg(&g_pooled[g * 64 + k]), __ldg(&Wc[o * 64 + k]), acc);
            out[t] = acc;
        }
        __syncthreads();                 // head reads complete before reset
        for (int t = tid; t < N_GRAPHS * 64; t += 256)
            reinterpret_cast<int*>(g_pooled)[t] = 0xFF800000;
        if (tid == 0) { g_done = 0; g_pooled_virgin = 1; }
    }
}

extern "C" void kernel_launch(void* const* d_in, const int* in_sizes, int n_in,
                              void* d_out, int out_size) {
    const float* pos  = (const float*)d_in[0];
    const int*   eidx = (const int*)  d_in[1];
    const int*   bat  = (const int*)  d_in[2];
    const float* W1   = (const float*)d_in[3];
    const float* b1   = (const float*)d_in[4];
    const float* W2   = (const float*)d_in[5];
    const float* b2   = (const float*)d_in[6];
    const float* Wc   = (const float*)d_in[7];
    const float* bc   = (const float*)d_in[8];
    float* out = (float*)d_out;

    const int* row = eidx;             // edge_index[0]
    const int* col = eidx + N_EDGES;   // edge_index[1]

    const int TB = 256;

    k_build<<<(N_EDGES / 8 + TB - 1) / TB, TB>>>((const int4*)row, (const int4*)col);
    k_prep <<<(N_NODES + TB - 1) / TB, TB>>>(pos);
    {
        int warps = (N_NODES + 1) / 2;                // 2 nodes per warp
        int blocks = (warps * 32 + TB - 1) / TB;
        k_gather1<<<blocks, TB>>>(W1, b1);
    }
    {
        int warps = (N_NODES + NPW - 1) / NPW;
        int blocks = (warps * 32 + TB - 1) / TB;
        k_gather2<<<blocks, TB>>>();
    }
    {
        int warps = (N_NODES + NTILE - 1) / NTILE;   // 6250
        int blocks = (warps + 7) / 8;                // 782
        k_mma_pool<<<blocks, TB>>>(W2, b2, bat, Wc, bc, out);
    }
}

// round 15
// speedup vs baseline: 1.4461x; 1.0170x over previous
#include <cuda_runtime.h>
#include <cuda_fp16.h>
#include <math.h>

#define N_NODES  100000
#define N_EDGES  3200000
#define N_GRAPHS 256
#define CAP      96        // P(in-degree >= 96) ~ e^-41 per node; multiple of 8
#define NPW      8         // nodes per warp in gather2 (even)
#define NTILE    16        // nodes per warp tile in mma_pool (m16)

// -------- scratch (device globals: zero-initialized at module load) --------
// State contract: every kernel_launch leaves deg/cur zeroed, pooled = -inf bits,
// done = 0 (reset in k_mma_pool epilogue), so graph replays are deterministic.
__device__ int    g_deg[N_NODES];                          // starts 0; deg = this + 1
__device__ int    g_cur[N_NODES];
__device__ float  g_dis[N_NODES];
__device__ __align__(16) int g_csr[N_NODES * CAP];         // padded to 8-mult with N_NODES
__device__ __align__(16) float g_ps[(N_NODES + 1) * 4];    // {d*p, d}; row N_NODES stays 0
__device__ __align__(16) __half g_h1[(N_NODES + 1) * 32];  // h1'; row N_NODES stays 0
__device__ __align__(16) __half g_agg2h[N_NODES * 32];     // layer-2 aggregate, fp16
__device__ float  g_pooled[N_GRAPHS * 64];                 // kept at -inf bits between runs
__device__ int    g_pooled_virgin;                         // 0 on first run
__device__ int    g_done;

__device__ __forceinline__ void red_add_s32(int* p, int v) {
    asm volatile("red.global.add.s32 [%0], %1;" :: "l"(p), "r"(v) : "memory");
}

// -------- build: 8 edges/thread; also first-run pooled init --------
__global__ void k_build(const int4* __restrict__ row4, const int4* __restrict__ col4) {
    int t = blockIdx.x * blockDim.x + threadIdx.x;
    if (t < N_GRAPHS * 64) {
        if (g_pooled_virgin == 0)
            reinterpret_cast<int*>(g_pooled)[t] = 0xFF800000;
    }
    if (t >= N_EDGES / 8) return;
#pragma unroll
    for (int u = 0; u < 2; u++) {
        int4 r = row4[t * 2 + u];
        int4 c = col4[t * 2 + u];
        red_add_s32(&g_deg[r.x], 1);
        red_add_s32(&g_deg[r.y], 1);
        red_add_s32(&g_deg[r.z], 1);
        red_add_s32(&g_deg[r.w], 1);
        int l0 = atomicAdd(&g_cur[c.x], 1);
        int l1 = atomicAdd(&g_cur[c.y], 1);
        int l2 = atomicAdd(&g_cur[c.z], 1);
        int l3 = atomicAdd(&g_cur[c.w], 1);
        if (l0 < CAP) g_csr[c.x * CAP + l0] = r.x;
        if (l1 < CAP) g_csr[c.y * CAP + l1] = r.y;
        if (l2 < CAP) g_csr[c.z * CAP + l2] = r.z;
        if (l3 < CAP) g_csr[c.w * CAP + l3] = r.w;
    }
}

// -------- prep (thread per node): d = rsqrt(deg+1), ps, csr pad to 8-mult --------
__global__ void k_prep(const float* __restrict__ pos) {
    int w = blockIdx.x * blockDim.x + threadIdx.x;
    if (w >= N_NODES) return;
    float d = rsqrtf((float)(g_deg[w] + 1));       // +1: self loop
    g_dis[w] = d;

    int cnt = min(g_cur[w], CAP);
    int padded = (cnt + 7) & ~7;
    for (int j = cnt; j < padded; j++) g_csr[w * CAP + j] = N_NODES;  // dummy

    float p0 = pos[w * 3 + 0], p1 = pos[w * 3 + 1], p2 = pos[w * 3 + 2];
    *reinterpret_cast<float4*>(&g_ps[w * 4]) = make_float4(d * p0, d * p1, d * p2, d);
}

// -------- layer 1: 2 nodes/warp interleaved (MLP=2), branchless dummy loads --------
__global__ void k_gather1(const float* __restrict__ W1, const float* __restrict__ b1) {
    int w = (blockIdx.x * blockDim.x + threadIdx.x) >> 5;
    int lane = threadIdx.x & 31;
    int i0 = w * 2;
    if (i0 >= N_NODES) return;
    int i1 = i0 + 1;
    bool v1 = (i1 < N_NODES);

    int cnt0 = min(g_cur[i0], CAP);
    int cnt1 = v1 ? min(g_cur[i1], CAP) : 0;
    int mx = max(cnt0, cnt1);
    const int* csr0 = &g_csr[i0 * CAP];
    const int* csr1 = &g_csr[i1 * CAP];

    float a0 = 0.f, a1 = 0.f, a2 = 0.f;
    float c0 = 0.f, c1 = 0.f, c2 = 0.f;
    for (int j = lane; j < mx; j += 32) {
        int r0 = (j < cnt0) ? __ldg(&csr0[j]) : N_NODES;
        int r1 = (j < cnt1) ? __ldg(&csr1[j]) : N_NODES;
        float4 p0 = *reinterpret_cast<const float4*>(&g_ps[r0 * 4]);  // dummy row = 0
        float4 p1 = *reinterpret_cast<const float4*>(&g_ps[r1 * 4]);
        a0 += p0.x; a1 += p0.y; a2 += p0.z;
        c0 += p1.x; c1 += p1.y; c2 += p1.z;
    }
#pragma unroll
    for (int s = 16; s > 0; s >>= 1) {
        a0 += __shfl_xor_sync(0xffffffff, a0, s);
        a1 += __shfl_xor_sync(0xffffffff, a1, s);
        a2 += __shfl_xor_sync(0xffffffff, a2, s);
        c0 += __shfl_xor_sync(0xffffffff, c0, s);
        c1 += __shfl_xor_sync(0xffffffff, c1, s);
        c2 += __shfl_xor_sync(0xffffffff, c2, s);
    }

    int o = lane;
    float w0 = __ldg(&W1[o * 3 + 0]);
    float w1v = __ldg(&W1[o * 3 + 1]);
    float w2v = __ldg(&W1[o * 3 + 2]);
    float bo = __ldg(&b1[o]);

    {
        float dc = g_dis[i0];
        float4 psc = *reinterpret_cast<const float4*>(&g_ps[i0 * 4]);
        float x0 = dc * (a0 + psc.x);
        float x1 = dc * (a1 + psc.y);
        float x2 = dc * (a2 + psc.z);
        float acc = bo + x0 * w0 + x1 * w1v + x2 * w2v;
        g_h1[i0 * 32 + o] = __float2half(dc * fmaxf(acc, 0.f));
    }
    if (v1) {
        float dc = g_dis[i1];
        float4 psc = *reinterpret_cast<const float4*>(&g_ps[i1 * 4]);
        float x0 = dc * (c0 + psc.x);
        float x1 = dc * (c1 + psc.y);
        float x2 = dc * (c2 + psc.z);
        float acc = bo + x0 * w0 + x1 * w1v + x2 * w2v;
        g_h1[i1 * 32 + o] = __float2half(dc * fmaxf(acc, 0.f));
    }
}

// Per-node gather body for layer 2: accumulates neighbor h1 rows into f0..f3
// (features q*4..q*4+3 across lanes), half2 inner accumulation flushed per 16 edges.
__device__ __forceinline__ void g2_accum(const int* __restrict__ csr, int padded,
                                         int grp, int q,
                                         float& f0, float& f1, float& f2, float& f3) {
    int p = 0;
    for (; p + 16 <= padded; p += 16) {
        __half2 h0 = __float2half2_rn(0.f), h1v = __float2half2_rn(0.f);
#pragma unroll
        for (int u = 0; u < 4; u++) {
            int r = __ldg(&csr[p + u * 4 + grp]);
            uint2 v = __ldg(reinterpret_cast<const uint2*>(g_h1 + r * 32) + q);
            h0  = __hadd2(h0,  *reinterpret_cast<__half2*>(&v.x));
            h1v = __hadd2(h1v, *reinterpret_cast<__half2*>(&v.y));
        }
        float2 fa = __half22float2(h0);
        float2 fb = __half22float2(h1v);
        f0 += fa.x; f1 += fa.y; f2 += fb.x; f3 += fb.y;
    }
    if (p < padded) {
        __half2 h0 = __float2half2_rn(0.f), h1v = __float2half2_rn(0.f);
#pragma unroll
        for (int u = 0; u < 2; u++) {
            int r = __ldg(&csr[p + u * 4 + grp]);
            uint2 v = __ldg(reinterpret_cast<const uint2*>(g_h1 + r * 32) + q);
            h0  = __hadd2(h0,  *reinterpret_cast<__half2*>(&v.x));
            h1v = __hadd2(h1v, *reinterpret_cast<__half2*>(&v.y));
        }
        float2 fa = __half22float2(h0);
        float2 fb = __half22float2(h1v);
        f0 += fa.x; f1 += fa.y; f2 += fb.x; f3 += fb.y;
    }
}

// -------- layer 2 gather: 2 nodes interleaved, 4 lanes/edge --------
__global__ void __launch_bounds__(256) k_gather2() {
    int warp = (blockIdx.x * blockDim.x + threadIdx.x) >> 5;
    int lane = threadIdx.x & 31;
    int grp  = lane >> 3;
    int q    = lane & 7;
    int base = warp * NPW;
    if (base >= N_NODES) return;

    for (int t = 0; t < NPW; t += 2) {
        int i0 = base + t;
        int i1 = i0 + 1;
        if (i0 >= N_NODES) break;
        bool v1 = (i1 < N_NODES);

        float a0 = 0.f, a1 = 0.f, a2 = 0.f, a3 = 0.f;
        float b0 = 0.f, b1 = 0.f, b2 = 0.f, b3 = 0.f;

        int pad0 = (min(g_cur[i0], CAP) + 7) & ~7;
        g2_accum(&g_csr[i0 * CAP], pad0, grp, q, a0, a1, a2, a3);
        if (v1) {
            int pad1 = (min(g_cur[i1], CAP) + 7) & ~7;
            g2_accum(&g_csr[i1 * CAP], pad1, grp, q, b0, b1, b2, b3);
        }

#pragma unroll
        for (int s = 8; s <= 16; s <<= 1) {
            a0 += __shfl_xor_sync(0xffffffff, a0, s);
            a1 += __shfl_xor_sync(0xffffffff, a1, s);
            a2 += __shfl_xor_sync(0xffffffff, a2, s);
            a3 += __shfl_xor_sync(0xffffffff, a3, s);
            b0 += __shfl_xor_sync(0xffffffff, b0, s);
            b1 += __shfl_xor_sync(0xffffffff, b1, s);
            b2 += __shfl_xor_sync(0xffffffff, b2, s);
            b3 += __shfl_xor_sync(0xffffffff, b3, s);
        }

        // self loops AFTER reduction (exactly once per feature)
        {
            uint2 v = __ldg(reinterpret_cast<const uint2*>(g_h1 + i0 * 32) + q);
            float2 fa = __half22float2(*reinterpret_cast<__half2*>(&v.x));
            float2 fb = __half22float2(*reinterpret_cast<__half2*>(&v.y));
            a0 += fa.x; a1 += fa.y; a2 += fb.x; a3 += fb.y;
        }
        if (v1) {
            uint2 v = __ldg(reinterpret_cast<const uint2*>(g_h1 + i1 * 32) + q);
            float2 fa = __half22float2(*reinterpret_cast<__half2*>(&v.x));
            float2 fb = __half22float2(*reinterpret_cast<__half2*>(&v.y));
            b0 += fa.x; b1 += fa.y; b2 += fb.x; b3 += fb.y;
        }

        if (lane < 8) {
            float d0 = g_dis[i0];
            __half2 o0 = __floats2half2_rn(d0 * a0, d0 * a1);
            __half2 o1 = __floats2half2_rn(d0 * a2, d0 * a3);
            uint2 w;
            w.x = *reinterpret_cast<unsigned*>(&o0);
            w.y = *reinterpret_cast<unsigned*>(&o1);
            *(reinterpret_cast<uint2*>(g_agg2h + i0 * 32) + q) = w;
            if (v1) {
                float d1 = g_dis[i1];
                __half2 p0 = __floats2half2_rn(d1 * b0, d1 * b1);
                __half2 p1 = __floats2half2_rn(d1 * b2, d1 * b3);
                uint2 u;
                u.x = *reinterpret_cast<unsigned*>(&p0);
                u.y = *reinterpret_cast<unsigned*>(&p1);
                *(reinterpret_cast<uint2*>(g_agg2h + i1 * 32) + q) = u;
            }
        }
    }
}

// -------- transform2 (HMMA) + relu + pool + head + state reset --------
__global__ void __launch_bounds__(256) k_mma_pool(const float* __restrict__ W2,
                                                  const float* __restrict__ b2,
                                                  const int*   __restrict__ batch,
                                                  const float* __restrict__ Wc,
                                                  const float* __restrict__ bc,
                                                  float*       __restrict__ out) {
    __shared__ __align__(16) __half sA[8 * 16 * 40];
    __shared__ __align__(16) __half sW2[32 * 72];

    int tid = threadIdx.x;
    int wid = tid >> 5;
    int lane = tid & 31;

    for (int x = tid; x < 32 * 64; x += 256) {
        int k = x >> 6, o = x & 63;
        sW2[k * 72 + o] = __float2half(__ldg(&W2[o * 32 + k]));
    }
    __syncthreads();

    int warp = blockIdx.x * 8 + wid;
    int base = warp * NTILE;

    if (base < N_NODES) {
        __half* Aw = &sA[wid * 16 * 40];
        const uint4* src = reinterpret_cast<const uint4*>(g_agg2h) + base * 4;
#pragma unroll
        for (int k = 0; k < 2; k++) {
            int c = lane + 32 * k;
            uint4 v = __ldg(&src[c]);
            *reinterpret_cast<uint4*>(reinterpret_cast<char*>(Aw) + (c >> 2) * 80 + (c & 3) * 16) = v;
        }
        __syncwarp();

        unsigned a0[4], a1[4];
        {
            unsigned ab = (unsigned)__cvta_generic_to_shared(Aw);
            unsigned addr0 = ab + (lane & 15) * 80 + (lane >> 4) * 16;
            asm volatile("ldmatrix.sync.aligned.m8n8.x4.shared.b16 {%0,%1,%2,%3}, [%4];"
                         : "=r"(a0[0]), "=r"(a0[1]), "=r"(a0[2]), "=r"(a0[3]) : "r"(addr0));
            unsigned addr1 = addr0 + 32;
            asm volatile("ldmatrix.sync.aligned.m8n8.x4.shared.b16 {%0,%1,%2,%3}, [%4];"
                         : "=r"(a1[0]), "=r"(a1[1]), "=r"(a1[2]), "=r"(a1[3]) : "r"(addr1));
        }

        float c[8][4];
#pragma unroll
        for (int n0 = 0; n0 < 8; n0++) { c[n0][0] = c[n0][1] = c[n0][2] = c[n0][3] = 0.f; }

        unsigned wb = (unsigned)__cvta_generic_to_shared(sW2);
#pragma unroll
        for (int n0 = 0; n0 < 8; n0++) {
            unsigned b0, b1;
            unsigned baddr0 = wb + (lane & 15) * 144 + n0 * 16;
            asm volatile("ldmatrix.sync.aligned.m8n8.x2.trans.shared.b16 {%0,%1}, [%2];"
                         : "=r"(b0), "=r"(b1) : "r"(baddr0));
            asm volatile("mma.sync.aligned.m16n8k16.row.col.f32.f16.f16.f32 "
                         "{%0,%1,%2,%3}, {%4,%5,%6,%7}, {%8,%9}, {%0,%1,%2,%3};"
                         : "+f"(c[n0][0]), "+f"(c[n0][1]), "+f"(c[n0][2]), "+f"(c[n0][3])
                         : "r"(a0[0]), "r"(a0[1]), "r"(a0[2]), "r"(a0[3]), "r"(b0), "r"(b1));
            unsigned baddr1 = wb + (16 + (lane & 15)) * 144 + n0 * 16;
            asm volatile("ldmatrix.sync.aligned.m8n8.x2.trans.shared.b16 {%0,%1}, [%2];"
                         : "=r"(b0), "=r"(b1) : "r"(baddr1));
            asm volatile("mma.sync.aligned.m16n8k16.row.col.f32.f16.f16.f32 "
                         "{%0,%1,%2,%3}, {%4,%5,%6,%7}, {%8,%9}, {%0,%1,%2,%3};"
                         : "+f"(c[n0][0]), "+f"(c[n0][1]), "+f"(c[n0][2]), "+f"(c[n0][3])
                         : "r"(a1[0]), "r"(a1[1]), "r"(a1[2]), "r"(a1[3]), "r"(b0), "r"(b1));
        }

        int q = lane & 3;
#pragma unroll
        for (int n0 = 0; n0 < 8; n0++) {
            float bx = __ldg(&b2[n0 * 8 + q * 2]);
            float by = __ldg(&b2[n0 * 8 + q * 2 + 1]);
            c[n0][0] = fmaxf(c[n0][0] + bx, 0.f);
            c[n0][1] = fmaxf(c[n0][1] + by, 0.f);
            c[n0][2] = fmaxf(c[n0][2] + bx, 0.f);
            c[n0][3] = fmaxf(c[n0][3] + by, 0.f);
        }

        int bA = __ldg(&batch[base + (lane >> 2)]);
        int bB = __ldg(&batch[base + 8 + (lane >> 2)]);
        int gfirst = __ldg(&batch[base]);
        int glast  = __ldg(&batch[base + 15]);

        for (int g = gfirst; g <= glast; g++) {
            bool m0 = (bA == g), m1 = (bB == g);
#pragma unroll
            for (int n0 = 0; n0 < 8; n0++) {
                float v0 = fmaxf(m0 ? c[n0][0] : 0.f, m1 ? c[n0][2] : 0.f);
                float v1 = fmaxf(m0 ? c[n0][1] : 0.f, m1 ? c[n0][3] : 0.f);
#pragma unroll
                for (int s = 4; s <= 16; s <<= 1) {
                    v0 = fmaxf(v0, __shfl_xor_sync(0xffffffff, v0, s));
                    v1 = fmaxf(v1, __shfl_xor_sync(0xffffffff, v1, s));
                }
                if (lane < 4) {
                    atomicMax(reinterpret_cast<int*>(&g_pooled[g * 64 + n0 * 8 + lane * 2]),
                              __float_as_int(v0));
                    atomicMax(reinterpret_cast<int*>(&g_pooled[g * 64 + n0 * 8 + lane * 2 + 1]),
                              __float_as_int(v1));
                }
            }
        }
    }

    // ---- state reset for next launch: deg/cur back to 0 ----
    for (int j = blockIdx.x * 256 + tid; j < N_NODES; j += gridDim.x * 256) {
        g_deg[j] = 0;
        g_cur[j] = 0;
    }

    // ---- last-block head + pooled/done reset ----
    __threadfence();
    __shared__ int sLast;
    if (tid == 0) sLast = (atomicAdd(&g_done, 1) == (int)gridDim.x - 1);
    __syncthreads();
    if (sLast) {
        for (int t = tid; t < N_GRAPHS * 2; t += 256) {
            int g = t >> 1;
            int o = t & 1;
            float acc = __ldg(&bc[o]);
#pragma unroll
            for (int k = 0; k < 64; k++)
                acc = fmaf(__ldcg(&g_pooled[g * 64 + k]), __ldg(&Wc[o * 64 + k]), acc);
            out[t] = acc;
        }
        __syncthreads();                 // head reads complete before reset
        for (int t = tid; t < N_GRAPHS * 64; t += 256)
            reinterpret_cast<int*>(g_pooled)[t] = 0xFF800000;
        if (tid == 0) { g_done = 0; g_pooled_virgin = 1; }
    }
}

extern "C" void kernel_launch(void* const* d_in, const int* in_sizes, int n_in,
                              void* d_out, int out_size) {
    const float* pos  = (const float*)d_in[0];
    const int*   eidx = (const int*)  d_in[1];
    const int*   bat  = (const int*)  d_in[2];
    const float* W1   = (const float*)d_in[3];
    const float* b1   = (const float*)d_in[4];
    const float* W2   = (const float*)d_in[5];
    const float* b2   = (const float*)d_in[6];
    const float* Wc   = (const float*)d_in[7];
    const float* bc   = (const float*)d_in[8];
    float* out = (float*)d_out;

    const int* row = eidx;             // edge_index[0]
    const int* col = eidx + N_EDGES;   // edge_index[1]

    const int TB = 256;

    k_build<<<(N_EDGES / 8 + TB - 1) / TB, TB>>>((const int4*)row, (const int4*)col);
    k_prep <<<(N_NODES + TB - 1) / TB, TB>>>(pos);
    {
        int warps = (N_NODES + 1) / 2;                // 2 nodes per warp
        int blocks = (warps * 32 + TB - 1) / TB;
        k_gather1<<<blocks, TB>>>(W1, b1);
    }
    {
        int warps = (N_NODES + NPW - 1) / NPW;        // 12500
        int blocks = (warps * 32 + TB - 1) / TB;      // 1563
        k_gather2<<<blocks, TB>>>();
    }
    {
        int warps = (N_NODES + NTILE - 1) / NTILE;   // 6250
        int blocks = (warps + 7) / 8;                // 782
        k_mma_pool<<<blocks, TB>>>(W2, b2, bat, Wc, bc, out);
    }
}

// round 16
// speedup vs baseline: 1.4599x; 1.0095x over previous
#include <cuda_runtime.h>
#include <cuda_fp16.h>
#include <math.h>

#define N_NODES  100000
#define N_EDGES  3200000
#define N_GRAPHS 256
#define CAP      96        // P(in-degree >= 96) ~ e^-41 per node; multiple of 8
#define NTILE    16        // nodes per warp tile in mma_pool (m16)

#define G2_BLOCKS    888   // 148 SMs x 6 blocks (40 regs, 256 thr) -> one exact wave
#define BUILD_BLOCKS 1184  // 148 SMs x 8 blocks

// -------- scratch (device globals: zero-initialized at module load) --------
// State contract: every kernel_launch leaves deg/cur zeroed, pooled = -inf bits,
// done = 0 (reset in k_mma_pool epilogue), so graph replays are deterministic.
__device__ int    g_deg[N_NODES];                          // starts 0; deg = this + 1
__device__ int    g_cur[N_NODES];
__device__ float  g_dis[N_NODES];
__device__ __align__(16) int g_csr[N_NODES * CAP];         // padded to 8-mult with N_NODES
__device__ __align__(16) float g_ps[(N_NODES + 1) * 4];    // {d*p, d}; row N_NODES stays 0
__device__ __align__(16) __half g_h1[(N_NODES + 1) * 32];  // h1'; row N_NODES stays 0
__device__ __align__(16) __half g_agg2h[N_NODES * 32];     // layer-2 aggregate, fp16
__device__ float  g_pooled[N_GRAPHS * 64];                 // kept at -inf bits between runs
__device__ int    g_pooled_virgin;                         // 0 on first run
__device__ int    g_done;

__device__ __forceinline__ void red_add_s32(int* p, int v) {
    asm volatile("red.global.add.s32 [%0], %1;" :: "l"(p), "r"(v) : "memory");
}

// -------- build: grid-stride over 4-edge quads; also first-run pooled init --------
__global__ void __launch_bounds__(256) k_build(const int4* __restrict__ row4,
                                               const int4* __restrict__ col4) {
    int t0 = blockIdx.x * blockDim.x + threadIdx.x;
    if (t0 < N_GRAPHS * 64) {
        if (g_pooled_virgin == 0)
            reinterpret_cast<int*>(g_pooled)[t0] = 0xFF800000;
    }
    int stride = gridDim.x * blockDim.x;
    for (int t = t0; t < N_EDGES / 4; t += stride) {
        int4 r = row4[t];
        int4 c = col4[t];
        red_add_s32(&g_deg[r.x], 1);
        red_add_s32(&g_deg[r.y], 1);
        red_add_s32(&g_deg[r.z], 1);
        red_add_s32(&g_deg[r.w], 1);
        int l0 = atomicAdd(&g_cur[c.x], 1);
        int l1 = atomicAdd(&g_cur[c.y], 1);
        int l2 = atomicAdd(&g_cur[c.z], 1);
        int l3 = atomicAdd(&g_cur[c.w], 1);
        if (l0 < CAP) g_csr[c.x * CAP + l0] = r.x;
        if (l1 < CAP) g_csr[c.y * CAP + l1] = r.y;
        if (l2 < CAP) g_csr[c.z * CAP + l2] = r.z;
        if (l3 < CAP) g_csr[c.w * CAP + l3] = r.w;
    }
}

// -------- prep (thread per node): d = rsqrt(deg+1), ps, csr pad to 8-mult --------
__global__ void k_prep(const float* __restrict__ pos) {
    int w = blockIdx.x * blockDim.x + threadIdx.x;
    if (w >= N_NODES) return;
    float d = rsqrtf((float)(g_deg[w] + 1));       // +1: self loop
    g_dis[w] = d;

    int cnt = min(g_cur[w], CAP);
    int padded = (cnt + 7) & ~7;
    for (int j = cnt; j < padded; j++) g_csr[w * CAP + j] = N_NODES;  // dummy

    float p0 = pos[w * 3 + 0], p1 = pos[w * 3 + 1], p2 = pos[w * 3 + 2];
    *reinterpret_cast<float4*>(&g_ps[w * 4]) = make_float4(d * p0, d * p1, d * p2, d);
}

// -------- layer 1: 2 nodes/warp interleaved (MLP=2), branchless dummy loads --------
__global__ void k_gather1(const float* __restrict__ W1, const float* __restrict__ b1) {
    int w = (blockIdx.x * blockDim.x + threadIdx.x) >> 5;
    int lane = threadIdx.x & 31;
    int i0 = w * 2;
    if (i0 >= N_NODES) return;
    int i1 = i0 + 1;
    bool v1 = (i1 < N_NODES);

    int cnt0 = min(g_cur[i0], CAP);
    int cnt1 = v1 ? min(g_cur[i1], CAP) : 0;
    int mx = max(cnt0, cnt1);
    const int* csr0 = &g_csr[i0 * CAP];
    const int* csr1 = &g_csr[i1 * CAP];

    float a0 = 0.f, a1 = 0.f, a2 = 0.f;
    float c0 = 0.f, c1 = 0.f, c2 = 0.f;
    for (int j = lane; j < mx; j += 32) {
        int r0 = (j < cnt0) ? __ldg(&csr0[j]) : N_NODES;
        int r1 = (j < cnt1) ? __ldg(&csr1[j]) : N_NODES;
        float4 p0 = *reinterpret_cast<const float4*>(&g_ps[r0 * 4]);  // dummy row = 0
        float4 p1 = *reinterpret_cast<const float4*>(&g_ps[r1 * 4]);
        a0 += p0.x; a1 += p0.y; a2 += p0.z;
        c0 += p1.x; c1 += p1.y; c2 += p1.z;
    }
#pragma unroll
    for (int s = 16; s > 0; s >>= 1) {
        a0 += __shfl_xor_sync(0xffffffff, a0, s);
        a1 += __shfl_xor_sync(0xffffffff, a1, s);
        a2 += __shfl_xor_sync(0xffffffff, a2, s);
        c0 += __shfl_xor_sync(0xffffffff, c0, s);
        c1 += __shfl_xor_sync(0xffffffff, c1, s);
        c2 += __shfl_xor_sync(0xffffffff, c2, s);
    }

    int o = lane;
    float w0 = __ldg(&W1[o * 3 + 0]);
    float w1v = __ldg(&W1[o * 3 + 1]);
    float w2v = __ldg(&W1[o * 3 + 2]);
    float bo = __ldg(&b1[o]);

    {
        float dc = g_dis[i0];
        float4 psc = *reinterpret_cast<const float4*>(&g_ps[i0 * 4]);
        float x0 = dc * (a0 + psc.x);
        float x1 = dc * (a1 + psc.y);
        float x2 = dc * (a2 + psc.z);
        float acc = bo + x0 * w0 + x1 * w1v + x2 * w2v;
        g_h1[i0 * 32 + o] = __float2half(dc * fmaxf(acc, 0.f));
    }
    if (v1) {
        float dc = g_dis[i1];
        float4 psc = *reinterpret_cast<const float4*>(&g_ps[i1 * 4]);
        float x0 = dc * (c0 + psc.x);
        float x1 = dc * (c1 + psc.y);
        float x2 = dc * (c2 + psc.z);
        float acc = bo + x0 * w0 + x1 * w1v + x2 * w2v;
        g_h1[i1 * 32 + o] = __float2half(dc * fmaxf(acc, 0.f));
    }
}

// Per-node gather body for layer 2: accumulates neighbor h1 rows into f0..f3
// (features q*4..q*4+3 across lanes), half2 inner accumulation flushed per 16 edges.
__device__ __forceinline__ void g2_accum(const int* __restrict__ csr, int padded,
                                         int grp, int q,
                                         float& f0, float& f1, float& f2, float& f3) {
    int p = 0;
    for (; p + 16 <= padded; p += 16) {
        __half2 h0 = __float2half2_rn(0.f), h1v = __float2half2_rn(0.f);
#pragma unroll
        for (int u = 0; u < 4; u++) {
            int r = __ldg(&csr[p + u * 4 + grp]);
            uint2 v = __ldg(reinterpret_cast<const uint2*>(g_h1 + r * 32) + q);
            h0  = __hadd2(h0,  *reinterpret_cast<__half2*>(&v.x));
            h1v = __hadd2(h1v, *reinterpret_cast<__half2*>(&v.y));
        }
        float2 fa = __half22float2(h0);
        float2 fb = __half22float2(h1v);
        f0 += fa.x; f1 += fa.y; f2 += fb.x; f3 += fb.y;
    }
    if (p < padded) {
        __half2 h0 = __float2half2_rn(0.f), h1v = __float2half2_rn(0.f);
#pragma unroll
        for (int u = 0; u < 2; u++) {
            int r = __ldg(&csr[p + u * 4 + grp]);
            uint2 v = __ldg(reinterpret_cast<const uint2*>(g_h1 + r * 32) + q);
            h0  = __hadd2(h0,  *reinterpret_cast<__half2*>(&v.x));
            h1v = __hadd2(h1v, *reinterpret_cast<__half2*>(&v.y));
        }
        float2 fa = __half22float2(h0);
        float2 fb = __half22float2(h1v);
        f0 += fa.x; f1 += fa.y; f2 += fb.x; f3 += fb.y;
    }
}

// -------- layer 2 gather: persistent warps, 2 nodes interleaved, 4 lanes/edge --------
__global__ void __launch_bounds__(256) k_gather2() {
    int gwarp  = (blockIdx.x * blockDim.x + threadIdx.x) >> 5;
    int nwarps = (gridDim.x * blockDim.x) >> 5;
    int lane = threadIdx.x & 31;
    int grp  = lane >> 3;
    int q    = lane & 7;

    const int npairs = (N_NODES + 1) / 2;
    for (int pr = gwarp; pr < npairs; pr += nwarps) {
        int i0 = pr * 2;
        int i1 = i0 + 1;
        bool v1 = (i1 < N_NODES);

        float a0 = 0.f, a1 = 0.f, a2 = 0.f, a3 = 0.f;
        float b0 = 0.f, b1 = 0.f, b2 = 0.f, b3 = 0.f;

        int pad0 = (min(g_cur[i0], CAP) + 7) & ~7;
        g2_accum(&g_csr[i0 * CAP], pad0, grp, q, a0, a1, a2, a3);
        if (v1) {
            int pad1 = (min(g_cur[i1], CAP) + 7) & ~7;
            g2_accum(&g_csr[i1 * CAP], pad1, grp, q, b0, b1, b2, b3);
        }

#pragma unroll
        for (int s = 8; s <= 16; s <<= 1) {
            a0 += __shfl_xor_sync(0xffffffff, a0, s);
            a1 += __shfl_xor_sync(0xffffffff, a1, s);
            a2 += __shfl_xor_sync(0xffffffff, a2, s);
            a3 += __shfl_xor_sync(0xffffffff, a3, s);
            b0 += __shfl_xor_sync(0xffffffff, b0, s);
            b1 += __shfl_xor_sync(0xffffffff, b1, s);
            b2 += __shfl_xor_sync(0xffffffff, b2, s);
            b3 += __shfl_xor_sync(0xffffffff, b3, s);
        }

        // self loops AFTER reduction (exactly once per feature)
        {
            uint2 v = __ldg(reinterpret_cast<const uint2*>(g_h1 + i0 * 32) + q);
            float2 fa = __half22float2(*reinterpret_cast<__half2*>(&v.x));
            float2 fb = __half22float2(*reinterpret_cast<__half2*>(&v.y));
            a0 += fa.x; a1 += fa.y; a2 += fb.x; a3 += fb.y;
        }
        if (v1) {
            uint2 v = __ldg(reinterpret_cast<const uint2*>(g_h1 + i1 * 32) + q);
            float2 fa = __half22float2(*reinterpret_cast<__half2*>(&v.x));
            float2 fb = __half22float2(*reinterpret_cast<__half2*>(&v.y));
            b0 += fa.x; b1 += fa.y; b2 += fb.x; b3 += fb.y;
        }

        if (lane < 8) {
            float d0 = g_dis[i0];
            __half2 o0 = __floats2half2_rn(d0 * a0, d0 * a1);
            __half2 o1 = __floats2half2_rn(d0 * a2, d0 * a3);
            uint2 w;
            w.x = *reinterpret_cast<unsigned*>(&o0);
            w.y = *reinterpret_cast<unsigned*>(&o1);
            *(reinterpret_cast<uint2*>(g_agg2h + i0 * 32) + q) = w;
            if (v1) {
                float d1 = g_dis[i1];
                __half2 p0 = __floats2half2_rn(d1 * b0, d1 * b1);
                __half2 p1 = __floats2half2_rn(d1 * b2, d1 * b3);
                uint2 u;
                u.x = *reinterpret_cast<unsigned*>(&p0);
                u.y = *reinterpret_cast<unsigned*>(&p1);
                *(reinterpret_cast<uint2*>(g_agg2h + i1 * 32) + q) = u;
            }
        }
    }
}

// -------- transform2 (HMMA) + relu + pool + head + state reset --------
__global__ void __launch_bounds__(256) k_mma_pool(const float* __restrict__ W2,
                                                  const float* __restrict__ b2,
                                                  const int*   __restrict__ batch,
                                                  const float* __restrict__ Wc,
                                                  const float* __restrict__ bc,
                                                  float*       __restrict__ out) {
    __shared__ __align__(16) __half sA[8 * 16 * 40];
    __shared__ __align__(16) __half sW2[32 * 72];

    int tid = threadIdx.x;
    int wid = tid >> 5;
    int lane = tid & 31;

    for (int x = tid; x < 32 * 64; x += 256) {
        int k = x >> 6, o = x & 63;
        sW2[k * 72 + o] = __float2half(__ldg(&W2[o * 32 + k]));
    }
    __syncthreads();

    int warp = blockIdx.x * 8 + wid;
    int base = warp * NTILE;

    if (base < N_NODES) {
        __half* Aw = &sA[wid * 16 * 40];
        const uint4* src = reinterpret_cast<const uint4*>(g_agg2h) + base * 4;
#pragma unroll
        for (int k = 0; k < 2; k++) {
            int c = lane + 32 * k;
            uint4 v = __ldg(&src[c]);
            *reinterpret_cast<uint4*>(reinterpret_cast<char*>(Aw) + (c >> 2) * 80 + (c & 3) * 16) = v;
        }
        __syncwarp();

        unsigned a0[4], a1[4];
        {
            unsigned ab = (unsigned)__cvta_generic_to_shared(Aw);
            unsigned addr0 = ab + (lane & 15) * 80 + (lane >> 4) * 16;
            asm volatile("ldmatrix.sync.aligned.m8n8.x4.shared.b16 {%0,%1,%2,%3}, [%4];"
                         : "=r"(a0[0]), "=r"(a0[1]), "=r"(a0[2]), "=r"(a0[3]) : "r"(addr0));
            unsigned addr1 = addr0 + 32;
            asm volatile("ldmatrix.sync.aligned.m8n8.x4.shared.b16 {%0,%1,%2,%3}, [%4];"
                         : "=r"(a1[0]), "=r"(a1[1]), "=r"(a1[2]), "=r"(a1[3]) : "r"(addr1));
        }

        float c[8][4];
#pragma unroll
        for (int n0 = 0; n0 < 8; n0++) { c[n0][0] = c[n0][1] = c[n0][2] = c[n0][3] = 0.f; }

        unsigned wb = (unsigned)__cvta_generic_to_shared(sW2);
#pragma unroll
        for (int n0 = 0; n0 < 8; n0++) {
            unsigned b0, b1;
            unsigned baddr0 = wb + (lane & 15) * 144 + n0 * 16;
            asm volatile("ldmatrix.sync.aligned.m8n8.x2.trans.shared.b16 {%0,%1}, [%2];"
                         : "=r"(b0), "=r"(b1) : "r"(baddr0));
            asm volatile("mma.sync.aligned.m16n8k16.row.col.f32.f16.f16.f32 "
                         "{%0,%1,%2,%3}, {%4,%5,%6,%7}, {%8,%9}, {%0,%1,%2,%3};"
                         : "+f"(c[n0][0]), "+f"(c[n0][1]), "+f"(c[n0][2]), "+f"(c[n0][3])
                         : "r"(a0[0]), "r"(a0[1]), "r"(a0[2]), "r"(a0[3]), "r"(b0), "r"(b1));
            unsigned baddr1 = wb + (16 + (lane & 15)) * 144 + n0 * 16;
            asm volatile("ldmatrix.sync.aligned.m8n8.x2.trans.shared.b16 {%0,%1}, [%2];"
                         : "=r"(b0), "=r"(b1) : "r"(baddr1));
            asm volatile("mma.sync.aligned.m16n8k16.row.col.f32.f16.f16.f32 "
                         "{%0,%1,%2,%3}, {%4,%5,%6,%7}, {%8,%9}, {%0,%1,%2,%3};"
                         : "+f"(c[n0][0]), "+f"(c[n0][1]), "+f"(c[n0][2]), "+f"(c[n0][3])
                         : "r"(a1[0]), "r"(a1[1]), "r"(a1[2]), "r"(a1[3]), "r"(b0), "r"(b1));
        }

        int q = lane & 3;
#pragma unroll
        for (int n0 = 0; n0 < 8; n0++) {
            float bx = __ldg(&b2[n0 * 8 + q * 2]);
            float by = __ldg(&b2[n0 * 8 + q * 2 + 1]);
            c[n0][0] = fmaxf(c[n0][0] + bx, 0.f);
            c[n0][1] = fmaxf(c[n0][1] + by, 0.f);
            c[n0][2] = fmaxf(c[n0][2] + bx, 0.f);
            c[n0][3] = fmaxf(c[n0][3] + by, 0.f);
        }

        int bA = __ldg(&batch[base + (lane >> 2)]);
        int bB = __ldg(&batch[base + 8 + (lane >> 2)]);
        int gfirst = __ldg(&batch[base]);
        int glast  = __ldg(&batch[base + 15]);

        for (int g = gfirst; g <= glast; g++) {
            bool m0 = (bA == g), m1 = (bB == g);
#pragma unroll
            for (int n0 = 0; n0 < 8; n0++) {
                float v0 = fmaxf(m0 ? c[n0][0] : 0.f, m1 ? c[n0][2] : 0.f);
                float v1 = fmaxf(m0 ? c[n0][1] : 0.f, m1 ? c[n0][3] : 0.f);
#pragma unroll
                for (int s = 4; s <= 16; s <<= 1) {
                    v0 = fmaxf(v0, __shfl_xor_sync(0xffffffff, v0, s));
                    v1 = fmaxf(v1, __shfl_xor_sync(0xffffffff, v1, s));
                }
                if (lane < 4) {
                    atomicMax(reinterpret_cast<int*>(&g_pooled[g * 64 + n0 * 8 + lane * 2]),
                              __float_as_int(v0));
                    atomicMax(reinterpret_cast<int*>(&g_pooled[g * 64 + n0 * 8 + lane * 2 + 1]),
                              __float_as_int(v1));
                }
            }
        }
    }

    // ---- state reset for next launch: deg/cur back to 0 ----
    for (int j = blockIdx.x * 256 + tid; j < N_NODES; j += gridDim.x * 256) {
        g_deg[j] = 0;
        g_cur[j] = 0;
    }

    // ---- last-block head + pooled/done reset ----
    __threadfence();
    __shared__ int sLast;
    if (tid == 0) sLast = (atomicAdd(&g_done, 1) == (int)gridDim.x - 1);
    __syncthreads();
    if (sLast) {
        for (int t = tid; t < N_GRAPHS * 2; t += 256) {
            int g = t >> 1;
            int o = t & 1;
            float acc = __ldg(&bc[o]);
#pragma unroll
            for (int k = 0; k < 64; k++)
                acc = fmaf(__ldcg(&g_pooled[g * 64 + k]), __ldg(&Wc[o * 64 + k]), acc);
            out[t] = acc;
        }
        __syncthreads();                 // head reads complete before reset
        for (int t = tid; t < N_GRAPHS * 64; t += 256)
            reinterpret_cast<int*>(g_pooled)[t] = 0xFF800000;
        if (tid == 0) { g_done = 0; g_pooled_virgin = 1; }
    }
}

extern "C" void kernel_launch(void* const* d_in, const int* in_sizes, int n_in,
                              void* d_out, int out_size) {
    const float* pos  = (const float*)d_in[0];
    const int*   eidx = (const int*)  d_in[1];
    const int*   bat  = (const int*)  d_in[2];
    const float* W1   = (const float*)d_in[3];
    const float* b1   = (const float*)d_in[4];
    const float* W2   = (const float*)d_in[5];
    const float* b2   = (const float*)d_in[6];
    const float* Wc   = (const float*)d_in[7];
    const float* bc   = (const float*)d_in[8];
    float* out = (float*)d_out;

    const int* row = eidx;             // edge_index[0]
    const int* col = eidx + N_EDGES;   // edge_index[1]

    const int TB = 256;

    k_build<<<BUILD_BLOCKS, TB>>>((const int4*)row, (const int4*)col);
    k_prep <<<(N_NODES + TB - 1) / TB, TB>>>(pos);
    {
        int warps = (N_NODES + 1) / 2;                // 2 nodes per warp
        int blocks = (warps * 32 + TB - 1) / TB;
        k_gather1<<<blocks, TB>>>(W1, b1);
    }
    k_gather2<<<G2_BLOCKS, TB>>>();
    {
        int warps = (N_NODES + NTILE - 1) / NTILE;   // 6250
        int blocks = (warps + 7) / 8;                // 782
        k_mma_pool<<<blocks, TB>>>(W2, b2, bat, Wc, bc, out);
    }
}